// round 6
// baseline (speedup 1.0000x reference)
#include <cuda_runtime.h>
#include <cstdint>

#define BATCH  16
#define NPTS   4096
#define NPT    1024
#define KNN    32
#define POSN   (BATCH*NPT*KNN)   // 524288 positions
#define NPAIR  (POSN/2)          // 262144 pairs
#define NTILES (POSN/64)         // 8192 tiles (32 pairs each)

// ---------------- scratch (device globals; no allocations allowed) ----------------
__device__ int    g_knn[POSN];
__device__ float  g_z[(size_t)POSN * 4];          // pair i: f4[2i]=(x0,x1,y0,y1), f4[2i+1]=(z0,z1,0,0)
__device__ float  g_y2[(size_t)POSN * 64];        // [NPAIR][64] float2 (pair-major)
__device__ float2 g_mm[(size_t)BATCH * NPT * 128];// per (b,s,c): (max_k, min_k) of pre-BN y3
__device__ double g_mom[9];                       // Sx,Sy,Sz,Sxx,Syy,Szz,Sxy,Sxz,Syz
__device__ double g_sum[3][128];
__device__ double g_sqs[3][128];
__device__ float  g_scale[3][128];
__device__ float  g_shift[3][128];

// ---- f32x2 helpers ----
__device__ __forceinline__ unsigned long long f2pack(float a, float b) {
    unsigned long long v;
    asm("mov.b64 %0, {%1, %2};" : "=l"(v) : "f"(a), "f"(b));
    return v;
}
__device__ __forceinline__ void f2unpack(unsigned long long v, float& a, float& b) {
    asm("mov.b64 {%0, %1}, %2;" : "=f"(a), "=f"(b) : "l"(v));
}
#define FMA2(d, a, b, c) \
    asm("fma.rn.f32x2 %0, %1, %2, %3;" : "=l"(d) : "l"(a), "l"(b), "l"(c))
#define ADD2(d, a, b) \
    asm("add.rn.f32x2 %0, %1, %2;" : "=l"(d) : "l"(a), "l"(b))
#define MUL2(d, a, b) \
    asm("mul.rn.f32x2 %0, %1, %2;" : "=l"(d) : "l"(a), "l"(b))

// ---------------- zero stats ----------------
__global__ void zero_stats_kernel() {
    int t = threadIdx.x;           // 512 threads
    if (t < 128)      { g_sum[1][t] = 0.0;       g_sqs[1][t] = 0.0; }
    else if (t < 256) { g_sum[2][t - 128] = 0.0; g_sqs[2][t - 128] = 0.0; }
    if (t < 9) g_mom[t] = 0.0;
}

// ---------------- farthest point sampling ----------------
// One block per batch, 256 threads, 16 points/thread (8 f32x2 pairs) in regs.
// Packed f32x2 distance math (IEEE-rn per lane; a-c as a+(-c) is bit-exact).
// Argmax keys (dist_bits<<32 | ~idx): per-thread depth-4 tree, warp shfl-max,
// one barrier, redundant 8-way final max. Exact jnp tie semantics.
__global__ void fps_kernel(const float* __restrict__ xyz,
                           const int* __restrict__ initf,
                           float* __restrict__ newxyz) {
    __shared__ unsigned long long wk[2][8];

    const int b = blockIdx.x, tid = threadIdx.x;
    const int lane = tid & 31, w = tid >> 5;
    const float* xb = xyz + (size_t)b * NPTS * 3;

    unsigned long long px2[8], py2[8], pz2[8];
    float dist[16];
    unsigned nid[16];
#pragma unroll
    for (int u = 0; u < 8; u++) {
        int p0 = tid + 256 * (2 * u);
        int p1 = tid + 256 * (2 * u + 1);
        px2[u] = f2pack(xb[3 * p0 + 0], xb[3 * p1 + 0]);
        py2[u] = f2pack(xb[3 * p0 + 1], xb[3 * p1 + 1]);
        pz2[u] = f2pack(xb[3 * p0 + 2], xb[3 * p1 + 2]);
        dist[2 * u] = 1e10f; dist[2 * u + 1] = 1e10f;
        nid[2 * u]     = 0xFFFFFFFFu - (unsigned)p0;
        nid[2 * u + 1] = 0xFFFFFFFFu - (unsigned)p1;
    }
    int f = initf[b];
    __syncthreads();

    for (int it = 0; it < NPT; it++) {
        float cx = xb[3 * f + 0], cy = xb[3 * f + 1], cz = xb[3 * f + 2];
        if (tid == 0) {
            float* o = newxyz + (size_t)(b * NPT + it) * 3;
            o[0] = cx; o[1] = cy; o[2] = cz;
        }
        unsigned long long ncx = f2pack(-cx, -cx);
        unsigned long long ncy = f2pack(-cy, -cy);
        unsigned long long ncz = f2pack(-cz, -cz);

        unsigned long long k[16];
#pragma unroll
        for (int u = 0; u < 8; u++) {
            unsigned long long dx, dy, dz, xx, yy, zz, ss, dd;
            ADD2(dx, px2[u], ncx);
            ADD2(dy, py2[u], ncy);
            ADD2(dz, pz2[u], ncz);
            MUL2(xx, dx, dx);
            MUL2(yy, dy, dy);
            MUL2(zz, dz, dz);
            ADD2(ss, xx, yy);
            ADD2(dd, ss, zz);
            float d0, d1;
            f2unpack(dd, d0, d1);
            dist[2 * u]     = fminf(dist[2 * u], d0);
            dist[2 * u + 1] = fminf(dist[2 * u + 1], d1);
            asm("mov.b64 %0, {%1, %2};"
                : "=l"(k[2 * u]) : "r"(nid[2 * u]), "r"(__float_as_uint(dist[2 * u])));
            asm("mov.b64 %0, {%1, %2};"
                : "=l"(k[2 * u + 1]) : "r"(nid[2 * u + 1]), "r"(__float_as_uint(dist[2 * u + 1])));
        }
#pragma unroll
        for (int o = 8; o; o >>= 1)
#pragma unroll
            for (int i = 0; i < 8; i++)
                if (i < o && k[i + o] > k[i]) k[i] = k[i + o];
        unsigned long long best = k[0];
#pragma unroll
        for (int o = 16; o; o >>= 1) {
            unsigned long long t = __shfl_xor_sync(0xFFFFFFFFu, best, o);
            if (t > best) best = t;
        }
        if (lane == 0) wk[it & 1][w] = best;
        __syncthreads();
        unsigned long long kk = wk[it & 1][0];
#pragma unroll
        for (int i = 1; i < 8; i++) {
            unsigned long long t = wk[it & 1][i];
            if (t > kk) kk = t;
        }
        f = (int)(0xFFFFFFFFu - (unsigned)(kk & 0xFFFFFFFFu));
    }
}

// ---------------- kNN (top-33 smallest, drop rank 0) ----------------
// Warp per query; register bitonic-32 + 33-step warp merge (exact stable order).
// Coord arrays aliased into the sl region (coords dead once r[] is built) ->
// 34KB smem/block -> more resident blocks to hide shfl-chain latency.
__global__ void knn_kernel(const float* __restrict__ newxyz) {
    __shared__ unsigned long long sl[128][33];   // padded: conflict-free
    float* qx = (float*)&sl[0][0];               // [0,4K) floats
    float* qy = qx + NPT;
    float* qz = qy + NPT;                        // 12KB < 33.8KB

    const int tid = threadIdx.x, lane = tid & 31, w = tid >> 5;
    const int b = blockIdx.x >> 8;
    const int s = ((blockIdx.x & 255) << 2) | w;
    const float* nb = newxyz + (size_t)b * NPT * 3;

    for (int i = tid; i < NPT; i += 128) {
        qx[i] = nb[3 * i + 0];
        qy[i] = nb[3 * i + 1];
        qz[i] = nb[3 * i + 2];
    }
    __syncthreads();

    const float x = qx[s], y = qy[s], z = qz[s];

    unsigned long long r[32];
#pragma unroll
    for (int u = 0; u < 32; u++) {
        int j = lane + 32 * u;
        float dx = __fsub_rn(qx[j], x);
        float dy = __fsub_rn(qy[j], y);
        float dz = __fsub_rn(qz[j], z);
        float d = __fadd_rn(__fadd_rn(__fmul_rn(dx, dx), __fmul_rn(dy, dy)),
                            __fmul_rn(dz, dz));
        r[u] = ((unsigned long long)__float_as_uint(d) << 32) | (unsigned)j;
    }
    __syncthreads();   // coords fully consumed; sl region may now be overwritten

#pragma unroll
    for (int k = 2; k <= 32; k <<= 1) {
#pragma unroll
        for (int j = k >> 1; j > 0; j >>= 1) {
#pragma unroll
            for (int i = 0; i < 32; i++) {
                int ixj = i ^ j;
                if (ixj > i) {
                    bool up = ((i & k) == 0);
                    unsigned long long a = r[i], bb = r[ixj];
                    if ((a > bb) == up) { r[i] = bb; r[ixj] = a; }
                }
            }
        }
    }

#pragma unroll
    for (int u = 0; u < 32; u++) sl[tid][u] = r[u];

    unsigned long long cand = r[0];
    int h = 1;
    int myidx = 0;
    for (int t = 0; t < 33; t++) {
        unsigned long long m = cand;
#pragma unroll
        for (int o = 16; o; o >>= 1) {
            unsigned long long v = __shfl_xor_sync(0xFFFFFFFFu, m, o);
            if (v < m) m = v;
        }
        if (t && lane == t - 1) myidx = (int)(unsigned)(m & 0xFFFFFFFFu);
        unsigned mask = __ballot_sync(0xFFFFFFFFu, cand == m);
        if (lane == __ffs(mask) - 1) {
            cand = (h < 32) ? sl[tid][h] : ~0ULL;
            h++;
        }
    }
    g_knn[(size_t)(b * NPT + s) * KNN + lane] = myidx;
}

// ---------------- grouping: gather z = xyz[knn] - center, 9 moments ----------------
__global__ void group_kernel(const float* __restrict__ xyz,
                             const float* __restrict__ newxyz) {
    __shared__ float wm[8][9];
    const int i = blockIdx.x * 256 + threadIdx.x;   // pair id < NPAIR
    int2 jj = ((const int2*)g_knn)[i];
    int bs = i >> 4;
    int b = bs >> 10;
    const float* np = newxyz + (size_t)bs * 3;
    float nx = np[0], ny = np[1], nz = np[2];
    const float* p0 = xyz + (size_t)(b * NPTS + jj.x) * 3;
    const float* p1 = xyz + (size_t)(b * NPTS + jj.y) * 3;
    float x0 = p0[0] - nx, y0 = p0[1] - ny, z0 = p0[2] - nz;
    float x1 = p1[0] - nx, y1 = p1[1] - ny, z1 = p1[2] - nz;
    float4* z4 = (float4*)g_z;
    z4[2 * i]     = make_float4(x0, x1, y0, y1);
    z4[2 * i + 1] = make_float4(z0, z1, 0.f, 0.f);

    float m[9] = { x0 + x1, y0 + y1, z0 + z1,
                   x0 * x0 + x1 * x1, y0 * y0 + y1 * y1, z0 * z0 + z1 * z1,
                   x0 * y0 + x1 * y1, x0 * z0 + x1 * z1, y0 * z0 + y1 * z1 };
#pragma unroll
    for (int u = 0; u < 9; u++) {
        float v = m[u];
#pragma unroll
        for (int o = 16; o; o >>= 1) v += __shfl_xor_sync(0xFFFFFFFFu, v, o);
        if ((threadIdx.x & 31) == 0) wm[threadIdx.x >> 5][u] = v;
    }
    __syncthreads();
    if (threadIdx.x < 9) {
        float s = 0.f;
#pragma unroll
        for (int ww = 0; ww < 8; ww++) s += wm[ww][threadIdx.x];
        atomicAdd(&g_mom[threadIdx.x], (double)s);
    }
}

// ---------------- BN1 stats from moments ----------------
__global__ void finalize1_kernel(const float* __restrict__ W1,
                                 const float* __restrict__ b1,
                                 const float* __restrict__ g1,
                                 const float* __restrict__ be1) {
    int c = threadIdx.x;   // 64
    double w0 = W1[3 * c], w1 = W1[3 * c + 1], w2 = W1[3 * c + 2], b = b1[c];
    double Sx = g_mom[0], Sy = g_mom[1], Sz = g_mom[2];
    double Sxx = g_mom[3], Syy = g_mom[4], Szz = g_mom[5];
    double Sxy = g_mom[6], Sxz = g_mom[7], Syz = g_mom[8];
    double N = (double)POSN;
    double ws = w0 * Sx + w1 * Sy + w2 * Sz;
    double mean = (ws + N * b) / N;
    double ey2 = (w0 * w0 * Sxx + w1 * w1 * Syy + w2 * w2 * Szz
                + 2.0 * (w0 * w1 * Sxy + w0 * w2 * Sxz + w1 * w2 * Syz)
                + 2.0 * b * ws + N * b * b) / N;
    double var = ey2 - mean * mean;
    if (var < 0.0) var = 0.0;
    float sc = g1[c] * rsqrtf((float)var + 1e-5f);
    g_scale[0][c] = sc;
    g_shift[0][c] = be1[c] - (float)mean * sc;
}

// ---------------- layer 2: recompute y1 from z + BN1 + ReLU, 64->64 GEMM ----------------
__global__ void __launch_bounds__(256)
layer2_kernel(const float* __restrict__ W, const float* __restrict__ bias,
              const float* __restrict__ W1, const float* __restrict__ b1) {
    __shared__ float4 zsh[64];                 // tile's z (32 pairs x 2 float4)
    __shared__ float2 tile2[32][66];           // [pair][ci], padded
    __shared__ float4 sw1[64];                 // (w0,w1,w2,b) per layer1 channel
    __shared__ float4 bnp[32];                 // (sc0,sh0,sc1,sh1) per channel pair
    __shared__ float red[256], red2[256];

    const int tid = threadIdx.x;
    const int c = tid & 63, q = tid >> 6;      // q<4, 8 pairs/thread
    if (tid < 64) sw1[tid] = make_float4(W1[3 * tid], W1[3 * tid + 1],
                                         W1[3 * tid + 2], b1[tid]);
    if (tid < 32) bnp[tid] = make_float4(g_scale[0][2 * tid], g_shift[0][2 * tid],
                                         g_scale[0][2 * tid + 1], g_shift[0][2 * tid + 1]);
    float wr[64];
#pragma unroll
    for (int i = 0; i < 64; i++) wr[i] = W[c * 64 + i];
    const unsigned long long bb2 = f2pack(bias[c], bias[c]);
    float s = 0.f, s2 = 0.f;
    __syncthreads();

    const float4* z4 = (const float4*)g_z;
    float2* yout = (float2*)g_y2;

    for (int tile = blockIdx.x; tile < NTILES; tile += gridDim.x) {
        if (tid < 64) zsh[tid] = z4[(size_t)tile * 64 + tid];
        __syncthreads();
#pragma unroll
        for (int rr = 0; rr < 4; rr++) {
            int e = tid + 256 * rr;
            int pair = e >> 5, ciq = e & 31;
            float4 xy = zsh[2 * pair];         // x0,x1,y0,y1
            float4 zz = zsh[2 * pair + 1];     // z0,z1,-,-
            float4 wv0 = sw1[2 * ciq], wv1 = sw1[2 * ciq + 1];
            float4 bn = bnp[ciq];
            float y00 = fmaf(wv0.x, xy.x, fmaf(wv0.y, xy.z, fmaf(wv0.z, zz.x, wv0.w)));
            float y01 = fmaf(wv0.x, xy.y, fmaf(wv0.y, xy.w, fmaf(wv0.z, zz.y, wv0.w)));
            float y10 = fmaf(wv1.x, xy.x, fmaf(wv1.y, xy.z, fmaf(wv1.z, zz.x, wv1.w)));
            float y11 = fmaf(wv1.x, xy.y, fmaf(wv1.y, xy.w, fmaf(wv1.z, zz.y, wv1.w)));
            float4 a;
            a.x = fmaxf(fmaf(y00, bn.x, bn.y), 0.f);
            a.y = fmaxf(fmaf(y01, bn.x, bn.y), 0.f);
            a.z = fmaxf(fmaf(y10, bn.z, bn.w), 0.f);
            a.w = fmaxf(fmaf(y11, bn.z, bn.w), 0.f);
            *(float4*)&tile2[pair][2 * ciq] = a;
        }
        __syncthreads();

        unsigned long long acc2[8];
#pragma unroll
        for (int m = 0; m < 8; m++) acc2[m] = bb2;
#pragma unroll
        for (int cq = 0; cq < 32; cq++) {
            unsigned long long wA = f2pack(wr[2 * cq], wr[2 * cq]);
            unsigned long long wB = f2pack(wr[2 * cq + 1], wr[2 * cq + 1]);
#pragma unroll
            for (int m = 0; m < 8; m++) {
                ulonglong2 zv = *(const ulonglong2*)&tile2[q * 8 + m][2 * cq];
                FMA2(acc2[m], wA, zv.x, acc2[m]);
                FMA2(acc2[m], wB, zv.y, acc2[m]);
            }
        }

        float2* yo = yout + ((size_t)tile * 32 + q * 8) * 64 + c;
#pragma unroll
        for (int m = 0; m < 8; m++) {
            float a0, a1;
            f2unpack(acc2[m], a0, a1);
            yo[(size_t)m * 64] = make_float2(a0, a1);
            s += a0 + a1;
            s2 += a0 * a0 + a1 * a1;
        }
        __syncthreads();
    }

    red[tid] = s; red2[tid] = s2;
    __syncthreads();
    if (tid < 128) { red[tid] += red[tid + 128]; red2[tid] += red2[tid + 128]; }
    __syncthreads();
    if (tid < 64) {
        atomicAdd(&g_sum[1][tid], (double)(red[tid] + red[tid + 64]));
        atomicAdd(&g_sqs[1][tid], (double)(red2[tid] + red2[tid + 64]));
    }
}

// ---------------- layer 3: BN2+ReLU on load, 64->128 GEMM, fused k-min/max ----------------
__global__ void __launch_bounds__(256)
layer3_kernel(const float* __restrict__ W, const float* __restrict__ bias) {
    __shared__ float2 tile2[32][66];
    __shared__ float4 bnp[32];
    __shared__ float red[256], red2[256];

    const int tid = threadIdx.x;
    const int c = tid & 127, q = tid >> 7;     // q<2, 16 pairs (= one s-group) / thread
    if (tid < 32) bnp[tid] = make_float4(g_scale[1][2 * tid], g_shift[1][2 * tid],
                                         g_scale[1][2 * tid + 1], g_shift[1][2 * tid + 1]);
    float wr[64];
#pragma unroll
    for (int i = 0; i < 64; i++) wr[i] = W[c * 64 + i];
    const unsigned long long bb2 = f2pack(bias[c], bias[c]);
    float s = 0.f, s2 = 0.f;
    __syncthreads();

    const float2* yin = (const float2*)g_y2;

    for (int tile = blockIdx.x; tile < NTILES; tile += gridDim.x) {
#pragma unroll
        for (int rr = 0; rr < 4; rr++) {
            int e = tid + 256 * rr;
            int pair = e >> 5, ciq = e & 31;
            float4 v = *(const float4*)(yin + ((size_t)tile * 32 + pair) * 64 + 2 * ciq);
            float4 bn = bnp[ciq];
            v.x = fmaxf(fmaf(v.x, bn.x, bn.y), 0.f);
            v.y = fmaxf(fmaf(v.y, bn.x, bn.y), 0.f);
            v.z = fmaxf(fmaf(v.z, bn.z, bn.w), 0.f);
            v.w = fmaxf(fmaf(v.w, bn.z, bn.w), 0.f);
            *(float4*)&tile2[pair][2 * ciq] = v;
        }
        __syncthreads();

        unsigned long long acc2[16];
#pragma unroll
        for (int m = 0; m < 16; m++) acc2[m] = bb2;
#pragma unroll
        for (int cq = 0; cq < 32; cq++) {
            unsigned long long wA = f2pack(wr[2 * cq], wr[2 * cq]);
            unsigned long long wB = f2pack(wr[2 * cq + 1], wr[2 * cq + 1]);
#pragma unroll
            for (int m = 0; m < 16; m++) {
                ulonglong2 zv = *(const ulonglong2*)&tile2[q * 16 + m][2 * cq];
                FMA2(acc2[m], wA, zv.x, acc2[m]);
                FMA2(acc2[m], wB, zv.y, acc2[m]);
            }
        }

        float mx = -3.402823466e38f, mn = 3.402823466e38f;
#pragma unroll
        for (int m = 0; m < 16; m++) {
            float a0, a1;
            f2unpack(acc2[m], a0, a1);
            s += a0 + a1;
            s2 += a0 * a0 + a1 * a1;
            mx = fmaxf(mx, fmaxf(a0, a1));
            mn = fminf(mn, fminf(a0, a1));
        }
        g_mm[((size_t)tile * 2 + q) * 128 + c] = make_float2(mx, mn);
        __syncthreads();
    }

    red[tid] = s; red2[tid] = s2;
    __syncthreads();
    if (tid < 128) {
        atomicAdd(&g_sum[2][tid], (double)(red[tid] + red[tid + 128]));
        atomicAdd(&g_sqs[2][tid], (double)(red2[tid] + red2[tid + 128]));
    }
}

// ---------------- BN finalize (layers 2,3) ----------------
__global__ void finalize_kernel(int l, const float* __restrict__ g,
                                const float* __restrict__ be, int C) {
    int c = threadIdx.x;
    if (c < C) {
        double n = (double)POSN;
        double m = g_sum[l][c] / n;
        double v = g_sqs[l][c] / n - m * m;
        if (v < 0.0) v = 0.0;
        float sc = g[c] * rsqrtf((float)v + 1e-5f);
        g_scale[l][c] = sc;
        g_shift[l][c] = be[c] - (float)m * sc;
    }
}

// ---------------- final: BN3+ReLU applied to max/min, transpose to [b,c,s] ----------------
__global__ void final_kernel(float* __restrict__ out) {
    __shared__ float t[128 * 33];
    __shared__ float ssc[128], ssh[128];
    const int blk = blockIdx.x;
    const int b = blk >> 5, st = blk & 31;
    const int tid = threadIdx.x;
    if (tid < 128) { ssc[tid] = g_scale[2][tid]; ssh[tid] = g_shift[2][tid]; }
    __syncthreads();
#pragma unroll
    for (int rr = 0; rr < 16; rr++) {
        int e = tid + 256 * rr;                 // 4096 = 32 s x 128 c
        int sl = e >> 7, cc = e & 127;
        float2 v = g_mm[((size_t)(b * NPT + st * 32 + sl)) * 128 + cc];
        float sc = ssc[cc], sh = ssh[cc];
        float val = (sc >= 0.f) ? fmaf(v.x, sc, sh) : fmaf(v.y, sc, sh);
        t[cc * 33 + sl] = fmaxf(val, 0.f);
    }
    __syncthreads();
#pragma unroll
    for (int rr = 0; rr < 16; rr++) {
        int e = tid + 256 * rr;
        int c2 = e >> 5, s2 = e & 31;
        out[(size_t)(b * 128 + c2) * NPT + st * 32 + s2] = t[c2 * 33 + s2];
    }
}

// ---------------- launch ----------------
extern "C" void kernel_launch(void* const* d_in, const int* in_sizes, int n_in,
                              void* d_out, int out_size) {
    const float* xyz   = (const float*)d_in[0];
    const int*   initf = (const int*)d_in[1];
    const float* W1 = (const float*)d_in[2];
    const float* b1 = (const float*)d_in[3];
    const float* g1 = (const float*)d_in[4];
    const float* be1 = (const float*)d_in[5];
    const float* W2 = (const float*)d_in[6];
    const float* b2 = (const float*)d_in[7];
    const float* g2 = (const float*)d_in[8];
    const float* be2 = (const float*)d_in[9];
    const float* W3 = (const float*)d_in[10];
    const float* b3 = (const float*)d_in[11];
    const float* g3 = (const float*)d_in[12];
    const float* be3 = (const float*)d_in[13];

    float* out = (float*)d_out;
    float* newxyz = out;                               // [16,1024,3]
    float* newpts = out + (size_t)BATCH * NPT * 3;     // [16,128,1024]

    zero_stats_kernel<<<1, 512>>>();
    fps_kernel<<<BATCH, 256>>>(xyz, initf, newxyz);
    knn_kernel<<<BATCH * 256, 128>>>(newxyz);
    group_kernel<<<NPAIR / 256, 256>>>(xyz, newxyz);
    finalize1_kernel<<<1, 64>>>(W1, b1, g1, be1);
    layer2_kernel<<<1184, 256>>>(W2, b2, W1, b1);
    finalize_kernel<<<1, 128>>>(1, g2, be2, 64);
    layer3_kernel<<<1184, 256>>>(W3, b3);
    finalize_kernel<<<1, 128>>>(2, g3, be3, 128);
    final_kernel<<<512, 256>>>(newpts);
}

// round 7
// speedup vs baseline: 1.1418x; 1.1418x over previous
#include <cuda_runtime.h>
#include <cstdint>

#define BATCH  16
#define NPTS   4096
#define NPT    1024
#define KNN    32
#define POSN   (BATCH*NPT*KNN)   // 524288 positions
#define NPAIR  (POSN/2)          // 262144 pairs
#define NTILES (POSN/64)         // 8192 tiles (32 pairs each)

// ---------------- scratch (device globals; no allocations allowed) ----------------
__device__ int    g_knn[POSN];
__device__ float  g_z[(size_t)POSN * 4];          // pair i: f4[2i]=(x0,x1,y0,y1), f4[2i+1]=(z0,z1,0,0)
__device__ float  g_y2[(size_t)POSN * 64];        // [NPAIR][64] float2 (pair-major)
__device__ float2 g_mm[(size_t)BATCH * NPT * 128];// per (b,s,c): (max_k, min_k) of pre-BN y3
__device__ double g_mom[9];                       // Sx,Sy,Sz,Sxx,Syy,Szz,Sxy,Sxz,Syz
__device__ double g_sum[3][128];
__device__ double g_sqs[3][128];
__device__ float  g_scale[3][128];
__device__ float  g_shift[3][128];

// ---- f32x2 helpers ----
__device__ __forceinline__ unsigned long long f2pack(float a, float b) {
    unsigned long long v;
    asm("mov.b64 %0, {%1, %2};" : "=l"(v) : "f"(a), "f"(b));
    return v;
}
__device__ __forceinline__ void f2unpack(unsigned long long v, float& a, float& b) {
    asm("mov.b64 {%0, %1}, %2;" : "=f"(a), "=f"(b) : "l"(v));
}
#define FMA2(d, a, b, c) \
    asm("fma.rn.f32x2 %0, %1, %2, %3;" : "=l"(d) : "l"(a), "l"(b), "l"(c))
#define ADD2(d, a, b) \
    asm("add.rn.f32x2 %0, %1, %2;" : "=l"(d) : "l"(a), "l"(b))
#define MUL2(d, a, b) \
    asm("mul.rn.f32x2 %0, %1, %2;" : "=l"(d) : "l"(a), "l"(b))

__device__ __forceinline__ unsigned long long u64max(unsigned long long a,
                                                     unsigned long long b) {
    return a > b ? a : b;
}

// ---------------- zero stats ----------------
__global__ void zero_stats_kernel() {
    int t = threadIdx.x;           // 512 threads
    if (t < 128)      { g_sum[1][t] = 0.0;       g_sqs[1][t] = 0.0; }
    else if (t < 256) { g_sum[2][t - 128] = 0.0; g_sqs[2][t - 128] = 0.0; }
    if (t < 9) g_mom[t] = 0.0;
}

// ---------------- farthest point sampling ----------------
// One block per batch, 256 threads, 16 points/thread (8 f32x2 pairs) in regs.
// Latency-optimized argmax: per-thread FMNMX value tree, REDUX.MAX on dist
// bits, tie-set REDUX.MIN on index (exact jnp semantics: max dist, min idx),
// depth-3 u64 tree over 8 warp partials. One barrier per iteration.
__global__ void fps_kernel(const float* __restrict__ xyz,
                           const int* __restrict__ initf,
                           float* __restrict__ newxyz) {
    __shared__ unsigned long long wk[2][8];

    const int b = blockIdx.x, tid = threadIdx.x;
    const int lane = tid & 31, w = tid >> 5;
    const float* xb = xyz + (size_t)b * NPTS * 3;

    unsigned long long px2[8], py2[8], pz2[8];
    float dist[16];
#pragma unroll
    for (int u = 0; u < 8; u++) {
        int p0 = tid + 256 * (2 * u);
        int p1 = tid + 256 * (2 * u + 1);
        px2[u] = f2pack(xb[3 * p0 + 0], xb[3 * p1 + 0]);
        py2[u] = f2pack(xb[3 * p0 + 1], xb[3 * p1 + 1]);
        pz2[u] = f2pack(xb[3 * p0 + 2], xb[3 * p1 + 2]);
        dist[2 * u] = 1e10f; dist[2 * u + 1] = 1e10f;
    }
    int f = initf[b];
    __syncthreads();

    for (int it = 0; it < NPT; it++) {
        float cx = xb[3 * f + 0], cy = xb[3 * f + 1], cz = xb[3 * f + 2];
        if (tid == 0) {
            float* o = newxyz + (size_t)(b * NPT + it) * 3;
            o[0] = cx; o[1] = cy; o[2] = cz;
        }
        unsigned long long ncx = f2pack(-cx, -cx);
        unsigned long long ncy = f2pack(-cy, -cy);
        unsigned long long ncz = f2pack(-cz, -cz);

#pragma unroll
        for (int u = 0; u < 8; u++) {
            unsigned long long dx, dy, dz, xx, yy, zz, ss, dd;
            ADD2(dx, px2[u], ncx);
            ADD2(dy, py2[u], ncy);
            ADD2(dz, pz2[u], ncz);
            MUL2(xx, dx, dx);
            MUL2(yy, dy, dy);
            MUL2(zz, dz, dz);
            ADD2(ss, xx, yy);
            ADD2(dd, ss, zz);
            float d0, d1;
            f2unpack(dd, d0, d1);
            dist[2 * u]     = fminf(dist[2 * u], d0);
            dist[2 * u + 1] = fminf(dist[2 * u + 1], d1);
        }
        // per-thread value max (FMNMX tree, depth 4)
        float t8[8], t4[4], t2[2];
#pragma unroll
        for (int i = 0; i < 8; i++) t8[i] = fmaxf(dist[i], dist[i + 8]);
#pragma unroll
        for (int i = 0; i < 4; i++) t4[i] = fmaxf(t8[i], t8[i + 4]);
        t2[0] = fmaxf(t4[0], t4[2]);
        t2[1] = fmaxf(t4[1], t4[3]);
        float dmax = fmaxf(t2[0], t2[1]);

        // warp max dist (u32 order valid: all dists nonneg)
        unsigned mw = __reduce_max_sync(0xFFFFFFFFu, __float_as_uint(dmax));

        // min index among this thread's slots hitting mw (IMNMX tree)
        unsigned ic[16];
#pragma unroll
        for (int j = 0; j < 16; j++)
            ic[j] = (__float_as_uint(dist[j]) == mw)
                      ? (unsigned)(tid + 256 * j) : 0xFFFFFFFFu;
#pragma unroll
        for (int o = 8; o; o >>= 1)
#pragma unroll
            for (int i = 0; i < 8; i++)
                if (i < o) ic[i] = umin(ic[i], ic[i + o]);
        unsigned widx = __reduce_min_sync(0xFFFFFFFFu, ic[0]);

        if (lane == 0)
            wk[it & 1][w] = ((unsigned long long)mw << 32) |
                            (unsigned)(0xFFFFFFFFu - widx);
        __syncthreads();

        const unsigned long long* W8 = wk[it & 1];
        unsigned long long v0 = u64max(W8[0], W8[1]);
        unsigned long long v1 = u64max(W8[2], W8[3]);
        unsigned long long v2 = u64max(W8[4], W8[5]);
        unsigned long long v3 = u64max(W8[6], W8[7]);
        unsigned long long kk = u64max(u64max(v0, v1), u64max(v2, v3));
        f = (int)(0xFFFFFFFFu - (unsigned)(kk & 0xFFFFFFFFu));
    }
}

// ---------------- kNN (top-33 smallest, drop rank 0) ----------------
// Warp per query; register bitonic-32 sort, then 33-step merge using
// REDUX min on dist bits + tie REDUX min on index (exact stable order;
// winner (dm,jm) is unique since j is unique).
__global__ void knn_kernel(const float* __restrict__ newxyz) {
    __shared__ unsigned long long sl[128][33];   // padded: conflict-free
    float* qx = (float*)&sl[0][0];               // coords aliased (dead after r[] built)
    float* qy = qx + NPT;
    float* qz = qy + NPT;

    const int tid = threadIdx.x, lane = tid & 31, w = tid >> 5;
    const int b = blockIdx.x >> 8;
    const int s = ((blockIdx.x & 255) << 2) | w;
    const float* nb = newxyz + (size_t)b * NPT * 3;

    for (int i = tid; i < NPT; i += 128) {
        qx[i] = nb[3 * i + 0];
        qy[i] = nb[3 * i + 1];
        qz[i] = nb[3 * i + 2];
    }
    __syncthreads();

    const float x = qx[s], y = qy[s], z = qz[s];

    unsigned long long r[32];
#pragma unroll
    for (int u = 0; u < 32; u++) {
        int j = lane + 32 * u;
        float dx = __fsub_rn(qx[j], x);
        float dy = __fsub_rn(qy[j], y);
        float dz = __fsub_rn(qz[j], z);
        float d = __fadd_rn(__fadd_rn(__fmul_rn(dx, dx), __fmul_rn(dy, dy)),
                            __fmul_rn(dz, dz));
        r[u] = ((unsigned long long)__float_as_uint(d) << 32) | (unsigned)j;
    }
    __syncthreads();   // coords consumed; sl may be overwritten

#pragma unroll
    for (int k = 2; k <= 32; k <<= 1) {
#pragma unroll
        for (int j = k >> 1; j > 0; j >>= 1) {
#pragma unroll
            for (int i = 0; i < 32; i++) {
                int ixj = i ^ j;
                if (ixj > i) {
                    bool up = ((i & k) == 0);
                    unsigned long long a = r[i], bb = r[ixj];
                    if ((a > bb) == up) { r[i] = bb; r[ixj] = a; }
                }
            }
        }
    }

#pragma unroll
    for (int u = 0; u < 32; u++) sl[tid][u] = r[u];

    unsigned ch = (unsigned)(r[0] >> 32);   // candidate dist bits
    unsigned cl = (unsigned)r[0];           // candidate index
    int h = 1;
    int myidx = 0;
    for (int t = 0; t < 33; t++) {
        unsigned dm = __reduce_min_sync(0xFFFFFFFFu, ch);
        unsigned jc = (ch == dm) ? cl : 0xFFFFFFFFu;
        unsigned jm = __reduce_min_sync(0xFFFFFFFFu, jc);
        if (t && lane == t - 1) myidx = (int)jm;
        if (ch == dm && cl == jm) {          // unique winner advances
            if (h < 32) {
                unsigned long long nx = sl[tid][h];
                ch = (unsigned)(nx >> 32);
                cl = (unsigned)nx;
            } else {
                ch = 0xFFFFFFFFu;            // sentinel (never a real dist)
                cl = 0xFFFFFFFFu;
            }
            h++;
        }
    }
    g_knn[(size_t)(b * NPT + s) * KNN + lane] = myidx;
}

// ---------------- grouping: gather z = xyz[knn] - center, 9 moments ----------------
__global__ void group_kernel(const float* __restrict__ xyz,
                             const float* __restrict__ newxyz) {
    __shared__ float wm[8][9];
    const int i = blockIdx.x * 256 + threadIdx.x;   // pair id < NPAIR
    int2 jj = ((const int2*)g_knn)[i];
    int bs = i >> 4;
    int b = bs >> 10;
    const float* np = newxyz + (size_t)bs * 3;
    float nx = np[0], ny = np[1], nz = np[2];
    const float* p0 = xyz + (size_t)(b * NPTS + jj.x) * 3;
    const float* p1 = xyz + (size_t)(b * NPTS + jj.y) * 3;
    float x0 = p0[0] - nx, y0 = p0[1] - ny, z0 = p0[2] - nz;
    float x1 = p1[0] - nx, y1 = p1[1] - ny, z1 = p1[2] - nz;
    float4* z4 = (float4*)g_z;
    z4[2 * i]     = make_float4(x0, x1, y0, y1);
    z4[2 * i + 1] = make_float4(z0, z1, 0.f, 0.f);

    float m[9] = { x0 + x1, y0 + y1, z0 + z1,
                   x0 * x0 + x1 * x1, y0 * y0 + y1 * y1, z0 * z0 + z1 * z1,
                   x0 * y0 + x1 * y1, x0 * z0 + x1 * z1, y0 * z0 + y1 * z1 };
#pragma unroll
    for (int u = 0; u < 9; u++) {
        float v = m[u];
#pragma unroll
        for (int o = 16; o; o >>= 1) v += __shfl_xor_sync(0xFFFFFFFFu, v, o);
        if ((threadIdx.x & 31) == 0) wm[threadIdx.x >> 5][u] = v;
    }
    __syncthreads();
    if (threadIdx.x < 9) {
        float s = 0.f;
#pragma unroll
        for (int ww = 0; ww < 8; ww++) s += wm[ww][threadIdx.x];
        atomicAdd(&g_mom[threadIdx.x], (double)s);
    }
}

// ---------------- BN1 stats from moments ----------------
__global__ void finalize1_kernel(const float* __restrict__ W1,
                                 const float* __restrict__ b1,
                                 const float* __restrict__ g1,
                                 const float* __restrict__ be1) {
    int c = threadIdx.x;   // 64
    double w0 = W1[3 * c], w1 = W1[3 * c + 1], w2 = W1[3 * c + 2], b = b1[c];
    double Sx = g_mom[0], Sy = g_mom[1], Sz = g_mom[2];
    double Sxx = g_mom[3], Syy = g_mom[4], Szz = g_mom[5];
    double Sxy = g_mom[6], Sxz = g_mom[7], Syz = g_mom[8];
    double N = (double)POSN;
    double ws = w0 * Sx + w1 * Sy + w2 * Sz;
    double mean = (ws + N * b) / N;
    double ey2 = (w0 * w0 * Sxx + w1 * w1 * Syy + w2 * w2 * Szz
                + 2.0 * (w0 * w1 * Sxy + w0 * w2 * Sxz + w1 * w2 * Syz)
                + 2.0 * b * ws + N * b * b) / N;
    double var = ey2 - mean * mean;
    if (var < 0.0) var = 0.0;
    float sc = g1[c] * rsqrtf((float)var + 1e-5f);
    g_scale[0][c] = sc;
    g_shift[0][c] = be1[c] - (float)mean * sc;
}

// ---------------- layer 2: recompute y1 from z + BN1 + ReLU, 64->64 GEMM ----------------
__global__ void __launch_bounds__(256)
layer2_kernel(const float* __restrict__ W, const float* __restrict__ bias,
              const float* __restrict__ W1, const float* __restrict__ b1) {
    __shared__ float4 zsh[64];                 // tile's z (32 pairs x 2 float4)
    __shared__ float2 tile2[32][66];           // [pair][ci], padded
    __shared__ float4 sw1[64];                 // (w0,w1,w2,b) per layer1 channel
    __shared__ float4 bnp[32];                 // (sc0,sh0,sc1,sh1) per channel pair
    __shared__ float red[256], red2[256];

    const int tid = threadIdx.x;
    const int c = tid & 63, q = tid >> 6;      // q<4, 8 pairs/thread
    if (tid < 64) sw1[tid] = make_float4(W1[3 * tid], W1[3 * tid + 1],
                                         W1[3 * tid + 2], b1[tid]);
    if (tid < 32) bnp[tid] = make_float4(g_scale[0][2 * tid], g_shift[0][2 * tid],
                                         g_scale[0][2 * tid + 1], g_shift[0][2 * tid + 1]);
    float wr[64];
#pragma unroll
    for (int i = 0; i < 64; i++) wr[i] = W[c * 64 + i];
    const unsigned long long bb2 = f2pack(bias[c], bias[c]);
    float s = 0.f, s2 = 0.f;
    __syncthreads();

    const float4* z4 = (const float4*)g_z;
    float2* yout = (float2*)g_y2;

    for (int tile = blockIdx.x; tile < NTILES; tile += gridDim.x) {
        if (tid < 64) zsh[tid] = z4[(size_t)tile * 64 + tid];
        __syncthreads();
#pragma unroll
        for (int rr = 0; rr < 4; rr++) {
            int e = tid + 256 * rr;
            int pair = e >> 5, ciq = e & 31;
            float4 xy = zsh[2 * pair];         // x0,x1,y0,y1
            float4 zz = zsh[2 * pair + 1];     // z0,z1,-,-
            float4 wv0 = sw1[2 * ciq], wv1 = sw1[2 * ciq + 1];
            float4 bn = bnp[ciq];
            float y00 = fmaf(wv0.x, xy.x, fmaf(wv0.y, xy.z, fmaf(wv0.z, zz.x, wv0.w)));
            float y01 = fmaf(wv0.x, xy.y, fmaf(wv0.y, xy.w, fmaf(wv0.z, zz.y, wv0.w)));
            float y10 = fmaf(wv1.x, xy.x, fmaf(wv1.y, xy.z, fmaf(wv1.z, zz.x, wv1.w)));
            float y11 = fmaf(wv1.x, xy.y, fmaf(wv1.y, xy.w, fmaf(wv1.z, zz.y, wv1.w)));
            float4 a;
            a.x = fmaxf(fmaf(y00, bn.x, bn.y), 0.f);
            a.y = fmaxf(fmaf(y01, bn.x, bn.y), 0.f);
            a.z = fmaxf(fmaf(y10, bn.z, bn.w), 0.f);
            a.w = fmaxf(fmaf(y11, bn.z, bn.w), 0.f);
            *(float4*)&tile2[pair][2 * ciq] = a;
        }
        __syncthreads();

        unsigned long long acc2[8];
#pragma unroll
        for (int m = 0; m < 8; m++) acc2[m] = bb2;
#pragma unroll
        for (int cq = 0; cq < 32; cq++) {
            unsigned long long wA = f2pack(wr[2 * cq], wr[2 * cq]);
            unsigned long long wB = f2pack(wr[2 * cq + 1], wr[2 * cq + 1]);
#pragma unroll
            for (int m = 0; m < 8; m++) {
                ulonglong2 zv = *(const ulonglong2*)&tile2[q * 8 + m][2 * cq];
                FMA2(acc2[m], wA, zv.x, acc2[m]);
                FMA2(acc2[m], wB, zv.y, acc2[m]);
            }
        }

        float2* yo = yout + ((size_t)tile * 32 + q * 8) * 64 + c;
#pragma unroll
        for (int m = 0; m < 8; m++) {
            float a0, a1;
            f2unpack(acc2[m], a0, a1);
            yo[(size_t)m * 64] = make_float2(a0, a1);
            s += a0 + a1;
            s2 += a0 * a0 + a1 * a1;
        }
        __syncthreads();
    }

    red[tid] = s; red2[tid] = s2;
    __syncthreads();
    if (tid < 128) { red[tid] += red[tid + 128]; red2[tid] += red2[tid + 128]; }
    __syncthreads();
    if (tid < 64) {
        atomicAdd(&g_sum[1][tid], (double)(red[tid] + red[tid + 64]));
        atomicAdd(&g_sqs[1][tid], (double)(red2[tid] + red2[tid + 64]));
    }
}

// ---------------- layer 3: BN2+ReLU on load, 64->128 GEMM, fused k-min/max ----------------
__global__ void __launch_bounds__(256)
layer3_kernel(const float* __restrict__ W, const float* __restrict__ bias) {
    __shared__ float2 tile2[32][66];
    __shared__ float4 bnp[32];
    __shared__ float red[256], red2[256];

    const int tid = threadIdx.x;
    const int c = tid & 127, q = tid >> 7;     // q<2, 16 pairs (= one s-group) / thread
    if (tid < 32) bnp[tid] = make_float4(g_scale[1][2 * tid], g_shift[1][2 * tid],
                                         g_scale[1][2 * tid + 1], g_shift[1][2 * tid + 1]);
    float wr[64];
#pragma unroll
    for (int i = 0; i < 64; i++) wr[i] = W[c * 64 + i];
    const unsigned long long bb2 = f2pack(bias[c], bias[c]);
    float s = 0.f, s2 = 0.f;
    __syncthreads();

    const float2* yin = (const float2*)g_y2;

    for (int tile = blockIdx.x; tile < NTILES; tile += gridDim.x) {
#pragma unroll
        for (int rr = 0; rr < 4; rr++) {
            int e = tid + 256 * rr;
            int pair = e >> 5, ciq = e & 31;
            float4 v = *(const float4*)(yin + ((size_t)tile * 32 + pair) * 64 + 2 * ciq);
            float4 bn = bnp[ciq];
            v.x = fmaxf(fmaf(v.x, bn.x, bn.y), 0.f);
            v.y = fmaxf(fmaf(v.y, bn.x, bn.y), 0.f);
            v.z = fmaxf(fmaf(v.z, bn.z, bn.w), 0.f);
            v.w = fmaxf(fmaf(v.w, bn.z, bn.w), 0.f);
            *(float4*)&tile2[pair][2 * ciq] = v;
        }
        __syncthreads();

        unsigned long long acc2[16];
#pragma unroll
        for (int m = 0; m < 16; m++) acc2[m] = bb2;
#pragma unroll
        for (int cq = 0; cq < 32; cq++) {
            unsigned long long wA = f2pack(wr[2 * cq], wr[2 * cq]);
            unsigned long long wB = f2pack(wr[2 * cq + 1], wr[2 * cq + 1]);
#pragma unroll
            for (int m = 0; m < 16; m++) {
                ulonglong2 zv = *(const ulonglong2*)&tile2[q * 16 + m][2 * cq];
                FMA2(acc2[m], wA, zv.x, acc2[m]);
                FMA2(acc2[m], wB, zv.y, acc2[m]);
            }
        }

        float mx = -3.402823466e38f, mn = 3.402823466e38f;
#pragma unroll
        for (int m = 0; m < 16; m++) {
            float a0, a1;
            f2unpack(acc2[m], a0, a1);
            s += a0 + a1;
            s2 += a0 * a0 + a1 * a1;
            mx = fmaxf(mx, fmaxf(a0, a1));
            mn = fminf(mn, fminf(a0, a1));
        }
        g_mm[((size_t)tile * 2 + q) * 128 + c] = make_float2(mx, mn);
        __syncthreads();
    }

    red[tid] = s; red2[tid] = s2;
    __syncthreads();
    if (tid < 128) {
        atomicAdd(&g_sum[2][tid], (double)(red[tid] + red[tid + 128]));
        atomicAdd(&g_sqs[2][tid], (double)(red2[tid] + red2[tid + 128]));
    }
}

// ---------------- BN finalize (layers 2,3) ----------------
__global__ void finalize_kernel(int l, const float* __restrict__ g,
                                const float* __restrict__ be, int C) {
    int c = threadIdx.x;
    if (c < C) {
        double n = (double)POSN;
        double m = g_sum[l][c] / n;
        double v = g_sqs[l][c] / n - m * m;
        if (v < 0.0) v = 0.0;
        float sc = g[c] * rsqrtf((float)v + 1e-5f);
        g_scale[l][c] = sc;
        g_shift[l][c] = be[c] - (float)m * sc;
    }
}

// ---------------- final: BN3+ReLU applied to max/min, transpose to [b,c,s] ----------------
__global__ void final_kernel(float* __restrict__ out) {
    __shared__ float t[128 * 33];
    __shared__ float ssc[128], ssh[128];
    const int blk = blockIdx.x;
    const int b = blk >> 5, st = blk & 31;
    const int tid = threadIdx.x;
    if (tid < 128) { ssc[tid] = g_scale[2][tid]; ssh[tid] = g_shift[2][tid]; }
    __syncthreads();
#pragma unroll
    for (int rr = 0; rr < 16; rr++) {
        int e = tid + 256 * rr;                 // 4096 = 32 s x 128 c
        int sl = e >> 7, cc = e & 127;
        float2 v = g_mm[((size_t)(b * NPT + st * 32 + sl)) * 128 + cc];
        float sc = ssc[cc], sh = ssh[cc];
        float val = (sc >= 0.f) ? fmaf(v.x, sc, sh) : fmaf(v.y, sc, sh);
        t[cc * 33 + sl] = fmaxf(val, 0.f);
    }
    __syncthreads();
#pragma unroll
    for (int rr = 0; rr < 16; rr++) {
        int e = tid + 256 * rr;
        int c2 = e >> 5, s2 = e & 31;
        out[(size_t)(b * 128 + c2) * NPT + st * 32 + s2] = t[c2 * 33 + s2];
    }
}

// ---------------- launch ----------------
extern "C" void kernel_launch(void* const* d_in, const int* in_sizes, int n_in,
                              void* d_out, int out_size) {
    const float* xyz   = (const float*)d_in[0];
    const int*   initf = (const int*)d_in[1];
    const float* W1 = (const float*)d_in[2];
    const float* b1 = (const float*)d_in[3];
    const float* g1 = (const float*)d_in[4];
    const float* be1 = (const float*)d_in[5];
    const float* W2 = (const float*)d_in[6];
    const float* b2 = (const float*)d_in[7];
    const float* g2 = (const float*)d_in[8];
    const float* be2 = (const float*)d_in[9];
    const float* W3 = (const float*)d_in[10];
    const float* b3 = (const float*)d_in[11];
    const float* g3 = (const float*)d_in[12];
    const float* be3 = (const float*)d_in[13];

    float* out = (float*)d_out;
    float* newxyz = out;                               // [16,1024,3]
    float* newpts = out + (size_t)BATCH * NPT * 3;     // [16,128,1024]

    zero_stats_kernel<<<1, 512>>>();
    fps_kernel<<<BATCH, 256>>>(xyz, initf, newxyz);
    knn_kernel<<<BATCH * 256, 128>>>(newxyz);
    group_kernel<<<NPAIR / 256, 256>>>(xyz, newxyz);
    finalize1_kernel<<<1, 64>>>(W1, b1, g1, be1);
    layer2_kernel<<<1184, 256>>>(W2, b2, W1, b1);
    finalize_kernel<<<1, 128>>>(1, g2, be2, 64);
    layer3_kernel<<<1184, 256>>>(W3, b3);
    finalize_kernel<<<1, 128>>>(2, g3, be3, 128);
    final_kernel<<<512, 256>>>(newpts);
}

// round 9
// speedup vs baseline: 1.1760x; 1.0299x over previous
#include <cuda_runtime.h>
#include <cstdint>

#define BATCH  16
#define NPTS   4096
#define NPT    1024
#define KNN    32
#define POSN   (BATCH*NPT*KNN)   // 524288 positions
#define NPAIR  (POSN/2)          // 262144 pairs
#define NTILES (POSN/64)         // 8192 tiles (32 pairs each)

// ---------------- scratch (device globals; no allocations allowed) ----------------
__device__ int    g_knn[POSN];
__device__ float  g_z[(size_t)POSN * 4];          // pair i: f4[2i]=(x0,x1,y0,y1), f4[2i+1]=(z0,z1,0,0)
__device__ float  g_y2[(size_t)POSN * 64];        // [NPAIR][64] float2 (pair-major)
__device__ float2 g_mm[(size_t)BATCH * NPT * 128];// per (b,s,c): (max_k, min_k) of pre-BN y3
__device__ double g_mom[9];                       // Sx,Sy,Sz,Sxx,Syy,Szz,Sxy,Sxz,Syz
__device__ double g_sum[3][128];
__device__ double g_sqs[3][128];
__device__ float  g_scale[3][128];
__device__ float  g_shift[3][128];

// ---- f32x2 helpers ----
__device__ __forceinline__ unsigned long long f2pack(float a, float b) {
    unsigned long long v;
    asm("mov.b64 %0, {%1, %2};" : "=l"(v) : "f"(a), "f"(b));
    return v;
}
__device__ __forceinline__ void f2unpack(unsigned long long v, float& a, float& b) {
    asm("mov.b64 {%0, %1}, %2;" : "=f"(a), "=f"(b) : "l"(v));
}
#define FMA2(d, a, b, c) \
    asm("fma.rn.f32x2 %0, %1, %2, %3;" : "=l"(d) : "l"(a), "l"(b), "l"(c))
#define ADD2(d, a, b) \
    asm("add.rn.f32x2 %0, %1, %2;" : "=l"(d) : "l"(a), "l"(b))
#define MUL2(d, a, b) \
    asm("mul.rn.f32x2 %0, %1, %2;" : "=l"(d) : "l"(a), "l"(b))

__device__ __forceinline__ unsigned long long u64max(unsigned long long a,
                                                     unsigned long long b) {
    return a > b ? a : b;
}

// ---------------- no-op (launch-slot alignment so ncu profiles fps) ----------------
__global__ void noop_kernel() {}

// ---------------- zero stats ----------------
__global__ void zero_stats_kernel() {
    int t = threadIdx.x;           // 512 threads
    if (t < 128)      { g_sum[1][t] = 0.0;       g_sqs[1][t] = 0.0; }
    else if (t < 256) { g_sum[2][t - 128] = 0.0; g_sqs[2][t - 128] = 0.0; }
    if (t < 9) g_mom[t] = 0.0;
}

// ---------------- farthest point sampling ----------------
// One block per batch, 256 threads, 16 points/thread (8 f32x2 pairs) in regs.
// Latency-optimized argmax: per-thread FMNMX value tree, REDUX.MAX on dist
// bits, tie-set REDUX.MIN on index (exact jnp semantics: max dist, min idx),
// depth-3 u64 tree over 8 warp partials. One barrier per iteration.
__global__ void fps_kernel(const float* __restrict__ xyz,
                           const int* __restrict__ initf,
                           float* __restrict__ newxyz) {
    __shared__ unsigned long long wk[2][8];

    const int b = blockIdx.x, tid = threadIdx.x;
    const int lane = tid & 31, w = tid >> 5;
    const float* xb = xyz + (size_t)b * NPTS * 3;

    unsigned long long px2[8], py2[8], pz2[8];
    float dist[16];
#pragma unroll
    for (int u = 0; u < 8; u++) {
        int p0 = tid + 256 * (2 * u);
        int p1 = tid + 256 * (2 * u + 1);
        px2[u] = f2pack(xb[3 * p0 + 0], xb[3 * p1 + 0]);
        py2[u] = f2pack(xb[3 * p0 + 1], xb[3 * p1 + 1]);
        pz2[u] = f2pack(xb[3 * p0 + 2], xb[3 * p1 + 2]);
        dist[2 * u] = 1e10f; dist[2 * u + 1] = 1e10f;
    }
    int f = initf[b];
    __syncthreads();

    for (int it = 0; it < NPT; it++) {
        float cx = xb[3 * f + 0], cy = xb[3 * f + 1], cz = xb[3 * f + 2];
        if (tid == 0) {
            float* o = newxyz + (size_t)(b * NPT + it) * 3;
            o[0] = cx; o[1] = cy; o[2] = cz;
        }
        unsigned long long ncx = f2pack(-cx, -cx);
        unsigned long long ncy = f2pack(-cy, -cy);
        unsigned long long ncz = f2pack(-cz, -cz);

#pragma unroll
        for (int u = 0; u < 8; u++) {
            unsigned long long dx, dy, dz, xx, yy, zz, ss, dd;
            ADD2(dx, px2[u], ncx);
            ADD2(dy, py2[u], ncy);
            ADD2(dz, pz2[u], ncz);
            MUL2(xx, dx, dx);
            MUL2(yy, dy, dy);
            MUL2(zz, dz, dz);
            ADD2(ss, xx, yy);
            ADD2(dd, ss, zz);
            float d0, d1;
            f2unpack(dd, d0, d1);
            dist[2 * u]     = fminf(dist[2 * u], d0);
            dist[2 * u + 1] = fminf(dist[2 * u + 1], d1);
        }
        // per-thread value max (FMNMX tree, depth 4)
        float t8[8], t4[4], t2[2];
#pragma unroll
        for (int i = 0; i < 8; i++) t8[i] = fmaxf(dist[i], dist[i + 8]);
#pragma unroll
        for (int i = 0; i < 4; i++) t4[i] = fmaxf(t8[i], t8[i + 4]);
        t2[0] = fmaxf(t4[0], t4[2]);
        t2[1] = fmaxf(t4[1], t4[3]);
        float dmax = fmaxf(t2[0], t2[1]);

        // warp max dist (u32 order valid: all dists nonneg)
        unsigned mw = __reduce_max_sync(0xFFFFFFFFu, __float_as_uint(dmax));

        // min index among this thread's slots hitting mw (IMNMX tree)
        unsigned ic[16];
#pragma unroll
        for (int j = 0; j < 16; j++)
            ic[j] = (__float_as_uint(dist[j]) == mw)
                      ? (unsigned)(tid + 256 * j) : 0xFFFFFFFFu;
#pragma unroll
        for (int o = 8; o; o >>= 1)
#pragma unroll
            for (int i = 0; i < 8; i++)
                if (i < o) ic[i] = umin(ic[i], ic[i + o]);
        unsigned widx = __reduce_min_sync(0xFFFFFFFFu, ic[0]);

        if (lane == 0)
            wk[it & 1][w] = ((unsigned long long)mw << 32) |
                            (unsigned)(0xFFFFFFFFu - widx);
        __syncthreads();

        const unsigned long long* W8 = wk[it & 1];
        unsigned long long v0 = u64max(W8[0], W8[1]);
        unsigned long long v1 = u64max(W8[2], W8[3]);
        unsigned long long v2 = u64max(W8[4], W8[5]);
        unsigned long long v3 = u64max(W8[6], W8[7]);
        unsigned long long kk = u64max(u64max(v0, v1), u64max(v2, v3));
        f = (int)(0xFFFFFFFFu - (unsigned)(kk & 0xFFFFFFFFu));
    }
}

// ---------------- kNN (top-33 smallest, drop rank 0) ----------------
// Warp per query; register bitonic-32 sort, then 33-step merge using
// REDUX min on dist bits + tie REDUX min on index (exact stable order).
__global__ void knn_kernel(const float* __restrict__ newxyz) {
    __shared__ unsigned long long sl[128][33];   // padded: conflict-free
    float* qx = (float*)&sl[0][0];               // coords aliased (dead after r[] built)
    float* qy = qx + NPT;
    float* qz = qy + NPT;

    const int tid = threadIdx.x, lane = tid & 31, w = tid >> 5;
    const int b = blockIdx.x >> 8;
    const int s = ((blockIdx.x & 255) << 2) | w;
    const float* nb = newxyz + (size_t)b * NPT * 3;

    for (int i = tid; i < NPT; i += 128) {
        qx[i] = nb[3 * i + 0];
        qy[i] = nb[3 * i + 1];
        qz[i] = nb[3 * i + 2];
    }
    __syncthreads();

    const float x = qx[s], y = qy[s], z = qz[s];

    unsigned long long r[32];
#pragma unroll
    for (int u = 0; u < 32; u++) {
        int j = lane + 32 * u;
        float dx = __fsub_rn(qx[j], x);
        float dy = __fsub_rn(qy[j], y);
        float dz = __fsub_rn(qz[j], z);
        float d = __fadd_rn(__fadd_rn(__fmul_rn(dx, dx), __fmul_rn(dy, dy)),
                            __fmul_rn(dz, dz));
        r[u] = ((unsigned long long)__float_as_uint(d) << 32) | (unsigned)j;
    }
    __syncthreads();   // coords consumed; sl may be overwritten

#pragma unroll
    for (int k = 2; k <= 32; k <<= 1) {
#pragma unroll
        for (int j = k >> 1; j > 0; j >>= 1) {
#pragma unroll
            for (int i = 0; i < 32; i++) {
                int ixj = i ^ j;
                if (ixj > i) {
                    bool up = ((i & k) == 0);
                    unsigned long long a = r[i], bb = r[ixj];
                    if ((a > bb) == up) { r[i] = bb; r[ixj] = a; }
                }
            }
        }
    }

#pragma unroll
    for (int u = 0; u < 32; u++) sl[tid][u] = r[u];

    unsigned ch = (unsigned)(r[0] >> 32);   // candidate dist bits
    unsigned cl = (unsigned)r[0];           // candidate index
    int h = 1;
    int myidx = 0;
    for (int t = 0; t < 33; t++) {
        unsigned dm = __reduce_min_sync(0xFFFFFFFFu, ch);
        unsigned jc = (ch == dm) ? cl : 0xFFFFFFFFu;
        unsigned jm = __reduce_min_sync(0xFFFFFFFFu, jc);
        if (t && lane == t - 1) myidx = (int)jm;
        if (ch == dm && cl == jm) {          // unique winner advances
            if (h < 32) {
                unsigned long long nx = sl[tid][h];
                ch = (unsigned)(nx >> 32);
                cl = (unsigned)nx;
            } else {
                ch = 0xFFFFFFFFu;            // sentinel (never a real dist)
                cl = 0xFFFFFFFFu;
            }
            h++;
        }
    }
    g_knn[(size_t)(b * NPT + s) * KNN + lane] = myidx;
}

// ---------------- grouping: gather z = xyz[knn] - center, 9 moments ----------------
__global__ void group_kernel(const float* __restrict__ xyz,
                             const float* __restrict__ newxyz) {
    __shared__ float wm[8][9];
    const int i = blockIdx.x * 256 + threadIdx.x;   // pair id < NPAIR
    int2 jj = ((const int2*)g_knn)[i];
    int bs = i >> 4;
    int b = bs >> 10;
    const float* np = newxyz + (size_t)bs * 3;
    float nx = np[0], ny = np[1], nz = np[2];
    const float* p0 = xyz + (size_t)(b * NPTS + jj.x) * 3;
    const float* p1 = xyz + (size_t)(b * NPTS + jj.y) * 3;
    float x0 = p0[0] - nx, y0 = p0[1] - ny, z0 = p0[2] - nz;
    float x1 = p1[0] - nx, y1 = p1[1] - ny, z1 = p1[2] - nz;
    float4* z4 = (float4*)g_z;
    z4[2 * i]     = make_float4(x0, x1, y0, y1);
    z4[2 * i + 1] = make_float4(z0, z1, 0.f, 0.f);

    float m[9] = { x0 + x1, y0 + y1, z0 + z1,
                   x0 * x0 + x1 * x1, y0 * y0 + y1 * y1, z0 * z0 + z1 * z1,
                   x0 * y0 + x1 * y1, x0 * z0 + x1 * z1, y0 * z0 + y1 * z1 };
#pragma unroll
    for (int u = 0; u < 9; u++) {
        float v = m[u];
#pragma unroll
        for (int o = 16; o; o >>= 1) v += __shfl_xor_sync(0xFFFFFFFFu, v, o);
        if ((threadIdx.x & 31) == 0) wm[threadIdx.x >> 5][u] = v;
    }
    __syncthreads();
    if (threadIdx.x < 9) {
        float s = 0.f;
#pragma unroll
        for (int ww = 0; ww < 8; ww++) s += wm[ww][threadIdx.x];
        atomicAdd(&g_mom[threadIdx.x], (double)s);
    }
}

// ---------------- BN1 stats from moments ----------------
__global__ void finalize1_kernel(const float* __restrict__ W1,
                                 const float* __restrict__ b1,
                                 const float* __restrict__ g1,
                                 const float* __restrict__ be1) {
    int c = threadIdx.x;   // 64
    double w0 = W1[3 * c], w1 = W1[3 * c + 1], w2 = W1[3 * c + 2], b = b1[c];
    double Sx = g_mom[0], Sy = g_mom[1], Sz = g_mom[2];
    double Sxx = g_mom[3], Syy = g_mom[4], Szz = g_mom[5];
    double Sxy = g_mom[6], Sxz = g_mom[7], Syz = g_mom[8];
    double N = (double)POSN;
    double ws = w0 * Sx + w1 * Sy + w2 * Sz;
    double mean = (ws + N * b) / N;
    double ey2 = (w0 * w0 * Sxx + w1 * w1 * Syy + w2 * w2 * Szz
                + 2.0 * (w0 * w1 * Sxy + w0 * w2 * Sxz + w1 * w2 * Syz)
                + 2.0 * b * ws + N * b * b) / N;
    double var = ey2 - mean * mean;
    if (var < 0.0) var = 0.0;
    float sc = g1[c] * rsqrtf((float)var + 1e-5f);
    g_scale[0][c] = sc;
    g_shift[0][c] = be1[c] - (float)mean * sc;
}

// ---------------- layer 2: recompute y1 from z + BN1 + ReLU, 64->64 GEMM ----------------
// Weights in shared as pre-packed (w,w) f32x2 -> ~64 fewer regs -> 3 blocks/SM.
__global__ void __launch_bounds__(256, 3)
layer2_kernel(const float* __restrict__ W, const float* __restrict__ bias,
              const float* __restrict__ W1, const float* __restrict__ b1) {
    __shared__ unsigned long long wsp[64][64];  // 32KB: [ci][c] = (W[c][ci], W[c][ci])
    __shared__ float4 zsh[64];                  // tile's z (32 pairs x 2 float4)
    __shared__ float2 tile2[32][66];            // [pair][ci], padded
    __shared__ float4 sw1[64];                  // (w0,w1,w2,b) per layer1 channel
    __shared__ float4 bnp[32];                  // (sc0,sh0,sc1,sh1) per channel pair
    __shared__ float red[256], red2[256];

    const int tid = threadIdx.x;
    const int c = tid & 63, q = tid >> 6;       // q<4, 8 pairs/thread
    if (tid < 64) sw1[tid] = make_float4(W1[3 * tid], W1[3 * tid + 1],
                                         W1[3 * tid + 2], b1[tid]);
    if (tid < 32) bnp[tid] = make_float4(g_scale[0][2 * tid], g_shift[0][2 * tid],
                                         g_scale[0][2 * tid + 1], g_shift[0][2 * tid + 1]);
#pragma unroll
    for (int e = tid; e < 4096; e += 256) {
        int ci = e >> 6, cc = e & 63;
        float wv = W[cc * 64 + ci];
        wsp[ci][cc] = f2pack(wv, wv);
    }
    const unsigned long long bb2 = f2pack(bias[c], bias[c]);
    float s = 0.f, s2 = 0.f;
    __syncthreads();

    const float4* z4 = (const float4*)g_z;
    float2* yout = (float2*)g_y2;

    for (int tile = blockIdx.x; tile < NTILES; tile += gridDim.x) {
        if (tid < 64) zsh[tid] = z4[(size_t)tile * 64 + tid];
        __syncthreads();
#pragma unroll
        for (int rr = 0; rr < 4; rr++) {
            int e = tid + 256 * rr;
            int pair = e >> 5, ciq = e & 31;
            float4 xy = zsh[2 * pair];          // x0,x1,y0,y1
            float4 zz = zsh[2 * pair + 1];      // z0,z1,-,-
            float4 wv0 = sw1[2 * ciq], wv1 = sw1[2 * ciq + 1];
            float4 bn = bnp[ciq];
            float y00 = fmaf(wv0.x, xy.x, fmaf(wv0.y, xy.z, fmaf(wv0.z, zz.x, wv0.w)));
            float y01 = fmaf(wv0.x, xy.y, fmaf(wv0.y, xy.w, fmaf(wv0.z, zz.y, wv0.w)));
            float y10 = fmaf(wv1.x, xy.x, fmaf(wv1.y, xy.z, fmaf(wv1.z, zz.x, wv1.w)));
            float y11 = fmaf(wv1.x, xy.y, fmaf(wv1.y, xy.w, fmaf(wv1.z, zz.y, wv1.w)));
            float4 a;
            a.x = fmaxf(fmaf(y00, bn.x, bn.y), 0.f);
            a.y = fmaxf(fmaf(y01, bn.x, bn.y), 0.f);
            a.z = fmaxf(fmaf(y10, bn.z, bn.w), 0.f);
            a.w = fmaxf(fmaf(y11, bn.z, bn.w), 0.f);
            *(float4*)&tile2[pair][2 * ciq] = a;
        }
        __syncthreads();

        unsigned long long acc2[8];
#pragma unroll
        for (int m = 0; m < 8; m++) acc2[m] = bb2;
#pragma unroll
        for (int cq = 0; cq < 32; cq++) {
            unsigned long long wA = wsp[2 * cq][c];
            unsigned long long wB = wsp[2 * cq + 1][c];
#pragma unroll
            for (int m = 0; m < 8; m++) {
                ulonglong2 zv = *(const ulonglong2*)&tile2[q * 8 + m][2 * cq];
                FMA2(acc2[m], wA, zv.x, acc2[m]);
                FMA2(acc2[m], wB, zv.y, acc2[m]);
            }
        }

        float2* yo = yout + ((size_t)tile * 32 + q * 8) * 64 + c;
#pragma unroll
        for (int m = 0; m < 8; m++) {
            float a0, a1;
            f2unpack(acc2[m], a0, a1);
            yo[(size_t)m * 64] = make_float2(a0, a1);
            s += a0 + a1;
            s2 += a0 * a0 + a1 * a1;
        }
        __syncthreads();
    }

    red[tid] = s; red2[tid] = s2;
    __syncthreads();
    if (tid < 128) { red[tid] += red[tid + 128]; red2[tid] += red2[tid + 128]; }
    __syncthreads();
    if (tid < 64) {
        atomicAdd(&g_sum[1][tid], (double)(red[tid] + red[tid + 64]));
        atomicAdd(&g_sqs[1][tid], (double)(red2[tid] + red2[tid + 64]));
    }
}

// ---------------- layer 3: BN2+ReLU on load, 64->128 GEMM, fused k-min/max ----------------
// Weights in shared (64KB) -> low regs -> 2 blocks/SM (smem-limited).
__global__ void __launch_bounds__(256, 2)
layer3_kernel(const float* __restrict__ W, const float* __restrict__ bias) {
    __shared__ unsigned long long wsp[64][128]; // 64KB: [ci][c] = (W[c][ci], W[c][ci])
    __shared__ float2 tile2[32][66];
    __shared__ float4 bnp[32];
    __shared__ float red[256], red2[256];

    const int tid = threadIdx.x;
    const int c = tid & 127, q = tid >> 7;      // q<2, 16 pairs (= one s-group) / thread
    if (tid < 32) bnp[tid] = make_float4(g_scale[1][2 * tid], g_shift[1][2 * tid],
                                         g_scale[1][2 * tid + 1], g_shift[1][2 * tid + 1]);
#pragma unroll
    for (int e = tid; e < 8192; e += 256) {
        int ci = e >> 7, cc = e & 127;
        float wv = W[cc * 64 + ci];
        wsp[ci][cc] = f2pack(wv, wv);
    }
    const unsigned long long bb2 = f2pack(bias[c], bias[c]);
    float s = 0.f, s2 = 0.f;
    __syncthreads();

    const float2* yin = (const float2*)g_y2;

    for (int tile = blockIdx.x; tile < NTILES; tile += gridDim.x) {
#pragma unroll
        for (int rr = 0; rr < 4; rr++) {
            int e = tid + 256 * rr;
            int pair = e >> 5, ciq = e & 31;
            float4 v = *(const float4*)(yin + ((size_t)tile * 32 + pair) * 64 + 2 * ciq);
            float4 bn = bnp[ciq];
            v.x = fmaxf(fmaf(v.x, bn.x, bn.y), 0.f);
            v.y = fmaxf(fmaf(v.y, bn.x, bn.y), 0.f);
            v.z = fmaxf(fmaf(v.z, bn.z, bn.w), 0.f);
            v.w = fmaxf(fmaf(v.w, bn.z, bn.w), 0.f);
            *(float4*)&tile2[pair][2 * ciq] = v;
        }
        __syncthreads();

        unsigned long long acc2[16];
#pragma unroll
        for (int m = 0; m < 16; m++) acc2[m] = bb2;
#pragma unroll
        for (int cq = 0; cq < 32; cq++) {
            unsigned long long wA = wsp[2 * cq][c];
            unsigned long long wB = wsp[2 * cq + 1][c];
#pragma unroll
            for (int m = 0; m < 16; m++) {
                ulonglong2 zv = *(const ulonglong2*)&tile2[q * 16 + m][2 * cq];
                FMA2(acc2[m], wA, zv.x, acc2[m]);
                FMA2(acc2[m], wB, zv.y, acc2[m]);
            }
        }

        float mx = -3.402823466e38f, mn = 3.402823466e38f;
#pragma unroll
        for (int m = 0; m < 16; m++) {
            float a0, a1;
            f2unpack(acc2[m], a0, a1);
            s += a0 + a1;
            s2 += a0 * a0 + a1 * a1;
            mx = fmaxf(mx, fmaxf(a0, a1));
            mn = fminf(mn, fminf(a0, a1));
        }
        g_mm[((size_t)tile * 2 + q) * 128 + c] = make_float2(mx, mn);
        __syncthreads();
    }

    red[tid] = s; red2[tid] = s2;
    __syncthreads();
    if (tid < 128) {
        atomicAdd(&g_sum[2][tid], (double)(red[tid] + red[tid + 128]));
        atomicAdd(&g_sqs[2][tid], (double)(red2[tid] + red2[tid + 128]));
    }
}

// ---------------- BN finalize (layers 2,3) ----------------
__global__ void finalize_kernel(int l, const float* __restrict__ g,
                                const float* __restrict__ be, int C) {
    int c = threadIdx.x;
    if (c < C) {
        double n = (double)POSN;
        double m = g_sum[l][c] / n;
        double v = g_sqs[l][c] / n - m * m;
        if (v < 0.0) v = 0.0;
        float sc = g[c] * rsqrtf((float)v + 1e-5f);
        g_scale[l][c] = sc;
        g_shift[l][c] = be[c] - (float)m * sc;
    }
}

// ---------------- final: BN3+ReLU applied to max/min, transpose to [b,c,s] ----------------
__global__ void final_kernel(float* __restrict__ out) {
    __shared__ float t[128 * 33];
    __shared__ float ssc[128], ssh[128];
    const int blk = blockIdx.x;
    const int b = blk >> 5, st = blk & 31;
    const int tid = threadIdx.x;
    if (tid < 128) { ssc[tid] = g_scale[2][tid]; ssh[tid] = g_shift[2][tid]; }
    __syncthreads();
#pragma unroll
    for (int rr = 0; rr < 16; rr++) {
        int e = tid + 256 * rr;                 // 4096 = 32 s x 128 c
        int sl = e >> 7, cc = e & 127;
        float2 v = g_mm[((size_t)(b * NPT + st * 32 + sl)) * 128 + cc];
        float sc = ssc[cc], sh = ssh[cc];
        float val = (sc >= 0.f) ? fmaf(v.x, sc, sh) : fmaf(v.y, sc, sh);
        t[cc * 33 + sl] = fmaxf(val, 0.f);
    }
    __syncthreads();
#pragma unroll
    for (int rr = 0; rr < 16; rr++) {
        int e = tid + 256 * rr;
        int c2 = e >> 5, s2 = e & 31;
        out[(size_t)(b * 128 + c2) * NPT + st * 32 + s2] = t[c2 * 33 + s2];
    }
}

// ---------------- launch ----------------
extern "C" void kernel_launch(void* const* d_in, const int* in_sizes, int n_in,
                              void* d_out, int out_size) {
    const float* xyz   = (const float*)d_in[0];
    const int*   initf = (const int*)d_in[1];
    const float* W1 = (const float*)d_in[2];
    const float* b1 = (const float*)d_in[3];
    const float* g1 = (const float*)d_in[4];
    const float* be1 = (const float*)d_in[5];
    const float* W2 = (const float*)d_in[6];
    const float* b2 = (const float*)d_in[7];
    const float* g2 = (const float*)d_in[8];
    const float* be2 = (const float*)d_in[9];
    const float* W3 = (const float*)d_in[10];
    const float* b3 = (const float*)d_in[11];
    const float* g3 = (const float*)d_in[12];
    const float* be3 = (const float*)d_in[13];

    float* out = (float*)d_out;
    float* newxyz = out;                               // [16,1024,3]
    float* newpts = out + (size_t)BATCH * NPT * 3;     // [16,128,1024]

    zero_stats_kernel<<<1, 512>>>();
    noop_kernel<<<1, 32>>>();                          // slot alignment:
    noop_kernel<<<1, 32>>>();                          // fps -> profiled slot 4
    fps_kernel<<<BATCH, 256>>>(xyz, initf, newxyz);
    knn_kernel<<<BATCH * 256, 128>>>(newxyz);
    group_kernel<<<NPAIR / 256, 256>>>(xyz, newxyz);
    finalize1_kernel<<<1, 64>>>(W1, b1, g1, be1);
    layer2_kernel<<<1184, 256>>>(W2, b2, W1, b1);
    finalize_kernel<<<1, 128>>>(1, g2, be2, 64);
    layer3_kernel<<<1184, 256>>>(W3, b3);
    finalize_kernel<<<1, 128>>>(2, g3, be3, 128);
    final_kernel<<<512, 256>>>(newpts);
}

// round 10
// speedup vs baseline: 1.2271x; 1.0435x over previous
#include <cuda_runtime.h>
#include <cstdint>

#define BATCH  16
#define NPTS   4096
#define NPT    1024
#define KNN    32
#define POSN   (BATCH*NPT*KNN)   // 524288 positions
#define NPAIR  (POSN/2)          // 262144 pairs
#define NTILES (POSN/64)         // 8192 tiles (32 pairs each)

// ---------------- scratch (device globals; no allocations allowed) ----------------
__device__ int    g_knn[POSN];
__device__ float  g_z[(size_t)POSN * 4];          // pair i: f4[2i]=(x0,x1,y0,y1), f4[2i+1]=(z0,z1,0,0)
__device__ float  g_y2[(size_t)POSN * 64];        // [NPAIR][64] float2 (pair-major)
__device__ float2 g_mm[(size_t)BATCH * NPT * 128];// per (b,s,c): (max_k, min_k) of pre-BN y3
__device__ double g_mom[9];                       // Sx,Sy,Sz,Sxx,Syy,Szz,Sxy,Sxz,Syz
__device__ double g_sum[3][128];
__device__ double g_sqs[3][128];
__device__ float  g_scale[3][128];
__device__ float  g_shift[3][128];

// ---- f32x2 helpers ----
__device__ __forceinline__ unsigned long long f2pack(float a, float b) {
    unsigned long long v;
    asm("mov.b64 %0, {%1, %2};" : "=l"(v) : "f"(a), "f"(b));
    return v;
}
__device__ __forceinline__ void f2unpack(unsigned long long v, float& a, float& b) {
    asm("mov.b64 {%0, %1}, %2;" : "=f"(a), "=f"(b) : "l"(v));
}
#define FMA2(d, a, b, c) \
    asm("fma.rn.f32x2 %0, %1, %2, %3;" : "=l"(d) : "l"(a), "l"(b), "l"(c))
#define ADD2(d, a, b) \
    asm("add.rn.f32x2 %0, %1, %2;" : "=l"(d) : "l"(a), "l"(b))
#define MUL2(d, a, b) \
    asm("mul.rn.f32x2 %0, %1, %2;" : "=l"(d) : "l"(a), "l"(b))

// ---------------- no-op (launch-slot alignment so ncu profiles fps) ----------------
__global__ void noop_kernel() {}

// ---------------- zero stats ----------------
__global__ void zero_stats_kernel() {
    int t = threadIdx.x;           // 512 threads
    if (t < 128)      { g_sum[1][t] = 0.0;       g_sqs[1][t] = 0.0; }
    else if (t < 256) { g_sum[2][t - 128] = 0.0; g_sqs[2][t - 128] = 0.0; }
    if (t < 9) g_mom[t] = 0.0;
}

// ---------------- farthest point sampling ----------------
// One block per batch, 1024 threads, 4 points/thread (2 f32x2 pairs) in regs.
// occ-optimized: 8 warps/SMSP hide REDUX/BAR/LDS latencies.
// Warp stage: REDUX.MAX(dist bits) + tie REDUX.MIN(index).
// Cross-warp stage: 32 partials (u32 dist / u32 idx), lane l loads partial l,
// same REDUX pair -> f computed redundantly in every warp. One barrier/iter
// (double-buffered partials). Exact jnp semantics (max dist, min index).
__global__ void fps_kernel(const float* __restrict__ xyz,
                           const int* __restrict__ initf,
                           float* __restrict__ newxyz) {
    __shared__ unsigned wkd[2][32], wki[2][32];

    const int b = blockIdx.x, tid = threadIdx.x;
    const int lane = tid & 31, w = tid >> 5;
    const float* xb = xyz + (size_t)b * NPTS * 3;

    unsigned long long px2[2], py2[2], pz2[2];
    float dist[4];
#pragma unroll
    for (int u = 0; u < 2; u++) {
        int p0 = tid + 1024 * (2 * u);
        int p1 = tid + 1024 * (2 * u + 1);
        px2[u] = f2pack(xb[3 * p0 + 0], xb[3 * p1 + 0]);
        py2[u] = f2pack(xb[3 * p0 + 1], xb[3 * p1 + 1]);
        pz2[u] = f2pack(xb[3 * p0 + 2], xb[3 * p1 + 2]);
        dist[2 * u] = 1e10f; dist[2 * u + 1] = 1e10f;
    }
    int f = initf[b];
    __syncthreads();

    for (int it = 0; it < NPT; it++) {
        float cx = xb[3 * f + 0], cy = xb[3 * f + 1], cz = xb[3 * f + 2];
        if (tid == 0) {
            float* o = newxyz + (size_t)(b * NPT + it) * 3;
            o[0] = cx; o[1] = cy; o[2] = cz;
        }
        unsigned long long ncx = f2pack(-cx, -cx);
        unsigned long long ncy = f2pack(-cy, -cy);
        unsigned long long ncz = f2pack(-cz, -cz);

#pragma unroll
        for (int u = 0; u < 2; u++) {
            unsigned long long dx, dy, dz, xx, yy, zz, ss, dd;
            ADD2(dx, px2[u], ncx);
            ADD2(dy, py2[u], ncy);
            ADD2(dz, pz2[u], ncz);
            MUL2(xx, dx, dx);
            MUL2(yy, dy, dy);
            MUL2(zz, dz, dz);
            ADD2(ss, xx, yy);
            ADD2(dd, ss, zz);
            float d0, d1;
            f2unpack(dd, d0, d1);
            dist[2 * u]     = fminf(dist[2 * u], d0);
            dist[2 * u + 1] = fminf(dist[2 * u + 1], d1);
        }
        // per-thread value max (depth 2)
        float dmax = fmaxf(fmaxf(dist[0], dist[1]), fmaxf(dist[2], dist[3]));

        // warp max dist (u32 order valid: all dists nonneg)
        unsigned mw = __reduce_max_sync(0xFFFFFFFFu, __float_as_uint(dmax));

        // min index among this thread's slots hitting mw
        unsigned ic[4];
#pragma unroll
        for (int j = 0; j < 4; j++)
            ic[j] = (__float_as_uint(dist[j]) == mw)
                      ? (unsigned)(tid + 1024 * j) : 0xFFFFFFFFu;
        unsigned widx = __reduce_min_sync(0xFFFFFFFFu,
                          umin(umin(ic[0], ic[1]), umin(ic[2], ic[3])));

        if (lane == 0) { wkd[it & 1][w] = mw; wki[it & 1][w] = widx; }
        __syncthreads();

        // cross-warp: lane l holds partial of warp l (exactly 32 warps)
        unsigned dl = wkd[it & 1][lane];
        unsigned il = wki[it & 1][lane];
        unsigned dm = __reduce_max_sync(0xFFFFFFFFu, dl);
        unsigned cand = (dl == dm) ? il : 0xFFFFFFFFu;
        f = (int)__reduce_min_sync(0xFFFFFFFFu, cand);
    }
}

// ---------------- kNN (top-33 smallest, drop rank 0) ----------------
// Warp per query; register bitonic-32 sort, then 33-step merge using
// REDUX min on dist bits + tie REDUX min on index (exact stable order).
__global__ void knn_kernel(const float* __restrict__ newxyz) {
    __shared__ unsigned long long sl[128][33];   // padded: conflict-free
    float* qx = (float*)&sl[0][0];               // coords aliased (dead after r[] built)
    float* qy = qx + NPT;
    float* qz = qy + NPT;

    const int tid = threadIdx.x, lane = tid & 31, w = tid >> 5;
    const int b = blockIdx.x >> 8;
    const int s = ((blockIdx.x & 255) << 2) | w;
    const float* nb = newxyz + (size_t)b * NPT * 3;

    for (int i = tid; i < NPT; i += 128) {
        qx[i] = nb[3 * i + 0];
        qy[i] = nb[3 * i + 1];
        qz[i] = nb[3 * i + 2];
    }
    __syncthreads();

    const float x = qx[s], y = qy[s], z = qz[s];

    unsigned long long r[32];
#pragma unroll
    for (int u = 0; u < 32; u++) {
        int j = lane + 32 * u;
        float dx = __fsub_rn(qx[j], x);
        float dy = __fsub_rn(qy[j], y);
        float dz = __fsub_rn(qz[j], z);
        float d = __fadd_rn(__fadd_rn(__fmul_rn(dx, dx), __fmul_rn(dy, dy)),
                            __fmul_rn(dz, dz));
        r[u] = ((unsigned long long)__float_as_uint(d) << 32) | (unsigned)j;
    }
    __syncthreads();   // coords consumed; sl may be overwritten

#pragma unroll
    for (int k = 2; k <= 32; k <<= 1) {
#pragma unroll
        for (int j = k >> 1; j > 0; j >>= 1) {
#pragma unroll
            for (int i = 0; i < 32; i++) {
                int ixj = i ^ j;
                if (ixj > i) {
                    bool up = ((i & k) == 0);
                    unsigned long long a = r[i], bb = r[ixj];
                    if ((a > bb) == up) { r[i] = bb; r[ixj] = a; }
                }
            }
        }
    }

#pragma unroll
    for (int u = 0; u < 32; u++) sl[tid][u] = r[u];

    unsigned ch = (unsigned)(r[0] >> 32);   // candidate dist bits
    unsigned cl = (unsigned)r[0];           // candidate index
    int h = 1;
    int myidx = 0;
    for (int t = 0; t < 33; t++) {
        unsigned dm = __reduce_min_sync(0xFFFFFFFFu, ch);
        unsigned jc = (ch == dm) ? cl : 0xFFFFFFFFu;
        unsigned jm = __reduce_min_sync(0xFFFFFFFFu, jc);
        if (t && lane == t - 1) myidx = (int)jm;
        if (ch == dm && cl == jm) {          // unique winner advances
            if (h < 32) {
                unsigned long long nx = sl[tid][h];
                ch = (unsigned)(nx >> 32);
                cl = (unsigned)nx;
            } else {
                ch = 0xFFFFFFFFu;            // sentinel (never a real dist)
                cl = 0xFFFFFFFFu;
            }
            h++;
        }
    }
    g_knn[(size_t)(b * NPT + s) * KNN + lane] = myidx;
}

// ---------------- grouping: gather z = xyz[knn] - center, 9 moments ----------------
__global__ void group_kernel(const float* __restrict__ xyz,
                             const float* __restrict__ newxyz) {
    __shared__ float wm[8][9];
    const int i = blockIdx.x * 256 + threadIdx.x;   // pair id < NPAIR
    int2 jj = ((const int2*)g_knn)[i];
    int bs = i >> 4;
    int b = bs >> 10;
    const float* np = newxyz + (size_t)bs * 3;
    float nx = np[0], ny = np[1], nz = np[2];
    const float* p0 = xyz + (size_t)(b * NPTS + jj.x) * 3;
    const float* p1 = xyz + (size_t)(b * NPTS + jj.y) * 3;
    float x0 = p0[0] - nx, y0 = p0[1] - ny, z0 = p0[2] - nz;
    float x1 = p1[0] - nx, y1 = p1[1] - ny, z1 = p1[2] - nz;
    float4* z4 = (float4*)g_z;
    z4[2 * i]     = make_float4(x0, x1, y0, y1);
    z4[2 * i + 1] = make_float4(z0, z1, 0.f, 0.f);

    float m[9] = { x0 + x1, y0 + y1, z0 + z1,
                   x0 * x0 + x1 * x1, y0 * y0 + y1 * y1, z0 * z0 + z1 * z1,
                   x0 * y0 + x1 * y1, x0 * z0 + x1 * z1, y0 * z0 + y1 * z1 };
#pragma unroll
    for (int u = 0; u < 9; u++) {
        float v = m[u];
#pragma unroll
        for (int o = 16; o; o >>= 1) v += __shfl_xor_sync(0xFFFFFFFFu, v, o);
        if ((threadIdx.x & 31) == 0) wm[threadIdx.x >> 5][u] = v;
    }
    __syncthreads();
    if (threadIdx.x < 9) {
        float s = 0.f;
#pragma unroll
        for (int ww = 0; ww < 8; ww++) s += wm[ww][threadIdx.x];
        atomicAdd(&g_mom[threadIdx.x], (double)s);
    }
}

// ---------------- BN1 stats from moments ----------------
__global__ void finalize1_kernel(const float* __restrict__ W1,
                                 const float* __restrict__ b1,
                                 const float* __restrict__ g1,
                                 const float* __restrict__ be1) {
    int c = threadIdx.x;   // 64
    double w0 = W1[3 * c], w1 = W1[3 * c + 1], w2 = W1[3 * c + 2], b = b1[c];
    double Sx = g_mom[0], Sy = g_mom[1], Sz = g_mom[2];
    double Sxx = g_mom[3], Syy = g_mom[4], Szz = g_mom[5];
    double Sxy = g_mom[6], Sxz = g_mom[7], Syz = g_mom[8];
    double N = (double)POSN;
    double ws = w0 * Sx + w1 * Sy + w2 * Sz;
    double mean = (ws + N * b) / N;
    double ey2 = (w0 * w0 * Sxx + w1 * w1 * Syy + w2 * w2 * Szz
                + 2.0 * (w0 * w1 * Sxy + w0 * w2 * Sxz + w1 * w2 * Syz)
                + 2.0 * b * ws + N * b * b) / N;
    double var = ey2 - mean * mean;
    if (var < 0.0) var = 0.0;
    float sc = g1[c] * rsqrtf((float)var + 1e-5f);
    g_scale[0][c] = sc;
    g_shift[0][c] = be1[c] - (float)mean * sc;
}

// ---------------- layer 2: recompute y1 from z + BN1 + ReLU, 64->64 GEMM ----------------
// Weights in shared as pre-packed (w,w) f32x2 -> ~64 fewer regs -> 3 blocks/SM.
__global__ void __launch_bounds__(256, 3)
layer2_kernel(const float* __restrict__ W, const float* __restrict__ bias,
              const float* __restrict__ W1, const float* __restrict__ b1) {
    __shared__ unsigned long long wsp[64][64];  // 32KB: [ci][c] = (W[c][ci], W[c][ci])
    __shared__ float4 zsh[64];                  // tile's z (32 pairs x 2 float4)
    __shared__ float2 tile2[32][66];            // [pair][ci], padded
    __shared__ float4 sw1[64];                  // (w0,w1,w2,b) per layer1 channel
    __shared__ float4 bnp[32];                  // (sc0,sh0,sc1,sh1) per channel pair
    __shared__ float red[256], red2[256];

    const int tid = threadIdx.x;
    const int c = tid & 63, q = tid >> 6;       // q<4, 8 pairs/thread
    if (tid < 64) sw1[tid] = make_float4(W1[3 * tid], W1[3 * tid + 1],
                                         W1[3 * tid + 2], b1[tid]);
    if (tid < 32) bnp[tid] = make_float4(g_scale[0][2 * tid], g_shift[0][2 * tid],
                                         g_scale[0][2 * tid + 1], g_shift[0][2 * tid + 1]);
#pragma unroll
    for (int e = tid; e < 4096; e += 256) {
        int ci = e >> 6, cc = e & 63;
        float wv = W[cc * 64 + ci];
        wsp[ci][cc] = f2pack(wv, wv);
    }
    const unsigned long long bb2 = f2pack(bias[c], bias[c]);
    float s = 0.f, s2 = 0.f;
    __syncthreads();

    const float4* z4 = (const float4*)g_z;
    float2* yout = (float2*)g_y2;

    for (int tile = blockIdx.x; tile < NTILES; tile += gridDim.x) {
        if (tid < 64) zsh[tid] = z4[(size_t)tile * 64 + tid];
        __syncthreads();
#pragma unroll
        for (int rr = 0; rr < 4; rr++) {
            int e = tid + 256 * rr;
            int pair = e >> 5, ciq = e & 31;
            float4 xy = zsh[2 * pair];          // x0,x1,y0,y1
            float4 zz = zsh[2 * pair + 1];      // z0,z1,-,-
            float4 wv0 = sw1[2 * ciq], wv1 = sw1[2 * ciq + 1];
            float4 bn = bnp[ciq];
            float y00 = fmaf(wv0.x, xy.x, fmaf(wv0.y, xy.z, fmaf(wv0.z, zz.x, wv0.w)));
            float y01 = fmaf(wv0.x, xy.y, fmaf(wv0.y, xy.w, fmaf(wv0.z, zz.y, wv0.w)));
            float y10 = fmaf(wv1.x, xy.x, fmaf(wv1.y, xy.z, fmaf(wv1.z, zz.x, wv1.w)));
            float y11 = fmaf(wv1.x, xy.y, fmaf(wv1.y, xy.w, fmaf(wv1.z, zz.y, wv1.w)));
            float4 a;
            a.x = fmaxf(fmaf(y00, bn.x, bn.y), 0.f);
            a.y = fmaxf(fmaf(y01, bn.x, bn.y), 0.f);
            a.z = fmaxf(fmaf(y10, bn.z, bn.w), 0.f);
            a.w = fmaxf(fmaf(y11, bn.z, bn.w), 0.f);
            *(float4*)&tile2[pair][2 * ciq] = a;
        }
        __syncthreads();

        unsigned long long acc2[8];
#pragma unroll
        for (int m = 0; m < 8; m++) acc2[m] = bb2;
#pragma unroll
        for (int cq = 0; cq < 32; cq++) {
            unsigned long long wA = wsp[2 * cq][c];
            unsigned long long wB = wsp[2 * cq + 1][c];
#pragma unroll
            for (int m = 0; m < 8; m++) {
                ulonglong2 zv = *(const ulonglong2*)&tile2[q * 8 + m][2 * cq];
                FMA2(acc2[m], wA, zv.x, acc2[m]);
                FMA2(acc2[m], wB, zv.y, acc2[m]);
            }
        }

        float2* yo = yout + ((size_t)tile * 32 + q * 8) * 64 + c;
#pragma unroll
        for (int m = 0; m < 8; m++) {
            float a0, a1;
            f2unpack(acc2[m], a0, a1);
            yo[(size_t)m * 64] = make_float2(a0, a1);
            s += a0 + a1;
            s2 += a0 * a0 + a1 * a1;
        }
        __syncthreads();
    }

    red[tid] = s; red2[tid] = s2;
    __syncthreads();
    if (tid < 128) { red[tid] += red[tid + 128]; red2[tid] += red2[tid + 128]; }
    __syncthreads();
    if (tid < 64) {
        atomicAdd(&g_sum[1][tid], (double)(red[tid] + red[tid + 64]));
        atomicAdd(&g_sqs[1][tid], (double)(red2[tid] + red2[tid + 64]));
    }
}

// ---------------- layer 3: BN2+ReLU on load, 64->128 GEMM, fused k-min/max ----------------
// Weights in shared (64KB) -> low regs -> 2 blocks/SM (smem-limited).
__global__ void __launch_bounds__(256, 2)
layer3_kernel(const float* __restrict__ W, const float* __restrict__ bias) {
    __shared__ unsigned long long wsp[64][128]; // 64KB: [ci][c] = (W[c][ci], W[c][ci])
    __shared__ float2 tile2[32][66];
    __shared__ float4 bnp[32];
    __shared__ float red[256], red2[256];

    const int tid = threadIdx.x;
    const int c = tid & 127, q = tid >> 7;      // q<2, 16 pairs (= one s-group) / thread
    if (tid < 32) bnp[tid] = make_float4(g_scale[1][2 * tid], g_shift[1][2 * tid],
                                         g_scale[1][2 * tid + 1], g_shift[1][2 * tid + 1]);
#pragma unroll
    for (int e = tid; e < 8192; e += 256) {
        int ci = e >> 7, cc = e & 127;
        float wv = W[cc * 64 + ci];
        wsp[ci][cc] = f2pack(wv, wv);
    }
    const unsigned long long bb2 = f2pack(bias[c], bias[c]);
    float s = 0.f, s2 = 0.f;
    __syncthreads();

    const float2* yin = (const float2*)g_y2;

    for (int tile = blockIdx.x; tile < NTILES; tile += gridDim.x) {
#pragma unroll
        for (int rr = 0; rr < 4; rr++) {
            int e = tid + 256 * rr;
            int pair = e >> 5, ciq = e & 31;
            float4 v = *(const float4*)(yin + ((size_t)tile * 32 + pair) * 64 + 2 * ciq);
            float4 bn = bnp[ciq];
            v.x = fmaxf(fmaf(v.x, bn.x, bn.y), 0.f);
            v.y = fmaxf(fmaf(v.y, bn.x, bn.y), 0.f);
            v.z = fmaxf(fmaf(v.z, bn.z, bn.w), 0.f);
            v.w = fmaxf(fmaf(v.w, bn.z, bn.w), 0.f);
            *(float4*)&tile2[pair][2 * ciq] = v;
        }
        __syncthreads();

        unsigned long long acc2[16];
#pragma unroll
        for (int m = 0; m < 16; m++) acc2[m] = bb2;
#pragma unroll
        for (int cq = 0; cq < 32; cq++) {
            unsigned long long wA = wsp[2 * cq][c];
            unsigned long long wB = wsp[2 * cq + 1][c];
#pragma unroll
            for (int m = 0; m < 16; m++) {
                ulonglong2 zv = *(const ulonglong2*)&tile2[q * 16 + m][2 * cq];
                FMA2(acc2[m], wA, zv.x, acc2[m]);
                FMA2(acc2[m], wB, zv.y, acc2[m]);
            }
        }

        float mx = -3.402823466e38f, mn = 3.402823466e38f;
#pragma unroll
        for (int m = 0; m < 16; m++) {
            float a0, a1;
            f2unpack(acc2[m], a0, a1);
            s += a0 + a1;
            s2 += a0 * a0 + a1 * a1;
            mx = fmaxf(mx, fmaxf(a0, a1));
            mn = fminf(mn, fminf(a0, a1));
        }
        g_mm[((size_t)tile * 2 + q) * 128 + c] = make_float2(mx, mn);
        __syncthreads();
    }

    red[tid] = s; red2[tid] = s2;
    __syncthreads();
    if (tid < 128) {
        atomicAdd(&g_sum[2][tid], (double)(red[tid] + red[tid + 128]));
        atomicAdd(&g_sqs[2][tid], (double)(red2[tid] + red2[tid + 128]));
    }
}

// ---------------- BN finalize (layers 2,3) ----------------
__global__ void finalize_kernel(int l, const float* __restrict__ g,
                                const float* __restrict__ be, int C) {
    int c = threadIdx.x;
    if (c < C) {
        double n = (double)POSN;
        double m = g_sum[l][c] / n;
        double v = g_sqs[l][c] / n - m * m;
        if (v < 0.0) v = 0.0;
        float sc = g[c] * rsqrtf((float)v + 1e-5f);
        g_scale[l][c] = sc;
        g_shift[l][c] = be[c] - (float)m * sc;
    }
}

// ---------------- final: BN3+ReLU applied to max/min, transpose to [b,c,s] ----------------
__global__ void final_kernel(float* __restrict__ out) {
    __shared__ float t[128 * 33];
    __shared__ float ssc[128], ssh[128];
    const int blk = blockIdx.x;
    const int b = blk >> 5, st = blk & 31;
    const int tid = threadIdx.x;
    if (tid < 128) { ssc[tid] = g_scale[2][tid]; ssh[tid] = g_shift[2][tid]; }
    __syncthreads();
#pragma unroll
    for (int rr = 0; rr < 16; rr++) {
        int e = tid + 256 * rr;                 // 4096 = 32 s x 128 c
        int sl = e >> 7, cc = e & 127;
        float2 v = g_mm[((size_t)(b * NPT + st * 32 + sl)) * 128 + cc];
        float sc = ssc[cc], sh = ssh[cc];
        float val = (sc >= 0.f) ? fmaf(v.x, sc, sh) : fmaf(v.y, sc, sh);
        t[cc * 33 + sl] = fmaxf(val, 0.f);
    }
    __syncthreads();
#pragma unroll
    for (int rr = 0; rr < 16; rr++) {
        int e = tid + 256 * rr;
        int c2 = e >> 5, s2 = e & 31;
        out[(size_t)(b * 128 + c2) * NPT + st * 32 + s2] = t[c2 * 33 + s2];
    }
}

// ---------------- launch ----------------
extern "C" void kernel_launch(void* const* d_in, const int* in_sizes, int n_in,
                              void* d_out, int out_size) {
    const float* xyz   = (const float*)d_in[0];
    const int*   initf = (const int*)d_in[1];
    const float* W1 = (const float*)d_in[2];
    const float* b1 = (const float*)d_in[3];
    const float* g1 = (const float*)d_in[4];
    const float* be1 = (const float*)d_in[5];
    const float* W2 = (const float*)d_in[6];
    const float* b2 = (const float*)d_in[7];
    const float* g2 = (const float*)d_in[8];
    const float* be2 = (const float*)d_in[9];
    const float* W3 = (const float*)d_in[10];
    const float* b3 = (const float*)d_in[11];
    const float* g3 = (const float*)d_in[12];
    const float* be3 = (const float*)d_in[13];

    float* out = (float*)d_out;
    float* newxyz = out;                               // [16,1024,3]
    float* newpts = out + (size_t)BATCH * NPT * 3;     // [16,128,1024]

    zero_stats_kernel<<<1, 512>>>();
    noop_kernel<<<1, 32>>>();                          // slot alignment:
    noop_kernel<<<1, 32>>>();                          // fps -> profiled slot 4
    fps_kernel<<<BATCH, 1024>>>(xyz, initf, newxyz);
    knn_kernel<<<BATCH * 256, 128>>>(newxyz);
    group_kernel<<<NPAIR / 256, 256>>>(xyz, newxyz);
    finalize1_kernel<<<1, 64>>>(W1, b1, g1, be1);
    layer2_kernel<<<1184, 256>>>(W2, b2, W1, b1);
    finalize_kernel<<<1, 128>>>(1, g2, be2, 64);
    layer3_kernel<<<1184, 256>>>(W3, b3);
    finalize_kernel<<<1, 128>>>(2, g3, be3, 128);
    final_kernel<<<512, 256>>>(newpts);
}